// round 12
// baseline (speedup 1.0000x reference)
#include <cuda_runtime.h>
#include <cuda_bf16.h>
#include <math.h>
#include <cstdint>

// ---------------- problem constants ----------------
#define B_  4
#define L_  4096
#define DM_ 512
#define KTOP 16
#define NBH 32            // B*H
#define NF 2049           // L/2+1
#define MTOT (B_*L_)      // 16384
#define NSEQ (B_*DM_)     // 2048 FFT series
#define NWEL (DM_*DM_)    // 262144 weight elements

typedef unsigned long long u64;
typedef unsigned int u32;

// ---------------- scratch (static __device__, no allocation) ----------------
__device__ float g_Qt[(size_t)B_*DM_*L_];    // Q time-major [(b*512+n)*4096+t]
__device__ float g_Kt[(size_t)B_*DM_*L_];    // K time-major
__device__ float g_V [(size_t)MTOT*DM_];     // V channel-major
__device__ float g_PP[(size_t)NSEQ*NF*2];    // per-series partial cross-spectra
__device__ float g_FS[NBH*NF*2];             // summed cross-spectrum
__device__ float g_W [NBH*KTOP];
__device__ int   g_D [NBH*KTOP];
__device__ float2 g_TW[4096];                // FFT twiddles exp(-2πik/4096)
__device__ __nv_bfloat16 g_XS[2][(size_t)MTOT*DM_];   // x split limbs
__device__ __nv_bfloat16 g_CS[2][(size_t)MTOT*DM_];   // ctx split limbs (gather output)
__device__ __nv_bfloat16 g_WS[4][2][NWEL];            // Wq,Wk,Wv,Wo split limbs

// ---------------- helpers ----------------
__device__ __forceinline__ u32 smem_u32(const void* p) {
    u32 a;
    asm("{ .reg .u64 t; cvta.to.shared.u64 t, %1; cvt.u32.u64 %0, t; }" : "=r"(a) : "l"(p));
    return a;
}
#define SWZ(x) ((u32)(x) ^ ((((u32)(x)) >> 3) & 0x70))

__device__ __forceinline__ void cp16(u32 dst, const void* src) {
    asm volatile("cp.async.cg.shared.global [%0], [%1], 16;" :: "r"(dst), "l"(src));
}
__device__ __forceinline__ void cp_commit() {
    asm volatile("cp.async.commit_group;" ::: "memory");
}
__device__ __forceinline__ void cp_wait1() {
    asm volatile("cp.async.wait_group 1;" ::: "memory");
}
__device__ __forceinline__ void cp_wait0() {
    asm volatile("cp.async.wait_group 0;" ::: "memory");
}
__device__ __forceinline__ void ldm_x4(u32* r, u32 addr) {
    asm volatile("ldmatrix.sync.aligned.m8n8.x4.shared.b16 {%0,%1,%2,%3}, [%4];"
        : "=r"(r[0]), "=r"(r[1]), "=r"(r[2]), "=r"(r[3]) : "r"(addr));
}
__device__ __forceinline__ void mma16816(float* d, const u32* a, u32 b0, u32 b1) {
    asm volatile(
        "mma.sync.aligned.m16n8k16.row.col.f32.bf16.bf16.f32 "
        "{%0,%1,%2,%3}, {%4,%5,%6,%7}, {%8,%9}, {%0,%1,%2,%3};"
        : "+f"(d[0]), "+f"(d[1]), "+f"(d[2]), "+f"(d[3])
        : "r"(a[0]), "r"(a[1]), "r"(a[2]), "r"(a[3]), "r"(b0), "r"(b1));
}

// ---------------- fused limb-split converts: x (8192 blocks) + 4 W (1024) ---
__global__ void convert_all_kernel(const float* __restrict__ x,
    const float* __restrict__ Wq, const float* __restrict__ Wk,
    const float* __restrict__ Wv, const float* __restrict__ Wo,
    __nv_bfloat16* __restrict__ XS0, __nv_bfloat16* __restrict__ XS1,
    __nv_bfloat16* __restrict__ WS)
{
    const float* src;
    __nv_bfloat16 *d0, *d1;
    int i;
    if (blockIdx.x < 8192) {
        src = x; d0 = XS0; d1 = XS1;
        i = blockIdx.x * 256 + threadIdx.x;
    } else {
        const int wblk = blockIdx.x - 8192;
        const int w = wblk >> 8;
        src = (w == 0) ? Wq : (w == 1) ? Wk : (w == 2) ? Wv : Wo;
        d0 = WS + (size_t)w * 2 * NWEL;
        d1 = d0 + NWEL;
        i = (wblk & 255) * 256 + threadIdx.x;
    }
    const float4 v = reinterpret_cast<const float4*>(src)[i];
    const float f[4] = {v.x, v.y, v.z, v.w};
    unsigned short h0[4], h1[4];
    #pragma unroll
    for (int j = 0; j < 4; j++) {
        __nv_bfloat16 b0 = __float2bfloat16(f[j]);
        float r = f[j] - __bfloat162float(b0);
        __nv_bfloat16 b1 = __float2bfloat16(r);
        h0[j] = __bfloat16_as_ushort(b0);
        h1[j] = __bfloat16_as_ushort(b1);
    }
    reinterpret_cast<uint2*>(d0)[i] = make_uint2((u32)h0[0] | ((u32)h0[1] << 16), (u32)h0[2] | ((u32)h0[3] << 16));
    reinterpret_cast<uint2*>(d1)[i] = make_uint2((u32)h1[0] | ((u32)h1[1] << 16), (u32)h1[2] | ((u32)h1[3] << 16));
}

// ---------------- setup: twiddles ----------------
__global__ void setup_kernel() {
    const int i = blockIdx.x * blockDim.x + threadIdx.x;
    if (i < 4096) {
        const double ang = -6.283185307179586476925 * (double)i / 4096.0;
        g_TW[i] = make_float2((float)cos(ang), (float)sin(ang));
    }
}

// ---------------- mma.sync split-bf16 GEMM body (3-term: 00,01,10) ----------
// CTA tile 64x128, 256 threads (2x4 warps, 32x32 warp tiles), k-chunk 64.
// Stage 48KB, double-buffered -> 96KB/CTA => 2 CTAs resident per SM.
#define STAGE_BYTES 49152     // A: 2 limbs x 8KB, B: 2 limbs x 16KB
__device__ __forceinline__ void gemm_body(
    const __nv_bfloat16* __restrict__ A0, const __nv_bfloat16* __restrict__ A1,
    const __nv_bfloat16* __restrict__ B0, const __nv_bfloat16* __restrict__ B1,
    const float* __restrict__ bias, float* __restrict__ out,
    const int transp, char* smem)
{
    const u32 sbase = smem_u32(smem);

    const int tid  = threadIdx.x;
    const int wid  = tid >> 5;
    const int lane = tid & 31;
    const int wm   = (wid & 1) * 32;     // warp m offset
    const int wn   = (wid >> 1) * 32;    // warp n offset
    const int m0   = blockIdx.x * 64;
    const int n0   = blockIdx.y * 128;

    const __nv_bfloat16* Ap[2] = {A0, A1};
    const __nv_bfloat16* Bp[2] = {B0, B1};

    float d[2][4][4];
    #pragma unroll
    for (int i = 0; i < 2; i++)
        #pragma unroll
        for (int j = 0; j < 4; j++)
            #pragma unroll
            for (int q = 0; q < 4; q++) d[i][j][q] = 0.0f;

    auto load_chunk = [&](int c, int stage) {
        const int k0 = c * 64;
        const u32 sb = sbase + stage * STAGE_BYTES;
        #pragma unroll
        for (int t = 0; t < 2; t++) {
            const char* gA = reinterpret_cast<const char*>(Ap[t]) + ((size_t)m0 * 512 + k0) * 2;
            const u32 sA = sb + t * 8192;
            #pragma unroll
            for (int i = 0; i < 2; i++) {            // 512 16B units (64 rows)
                const int u = tid + i * 256;
                const int row = u >> 3, cu = u & 7;
                cp16(sA + SWZ(row * 128 + cu * 16), gA + (size_t)row * 1024 + cu * 16);
            }
            const char* gB = reinterpret_cast<const char*>(Bp[t]) + ((size_t)n0 * 512 + k0) * 2;
            const u32 sB = sb + 16384 + t * 16384;
            #pragma unroll
            for (int i = 0; i < 4; i++) {            // 1024 16B units (128 rows)
                const int u = tid + i * 256;
                const int row = u >> 3, cu = u & 7;
                cp16(sB + SWZ(row * 128 + cu * 16), gB + (size_t)row * 1024 + cu * 16);
            }
        }
    };

    auto compute_chunk = [&](int stage) {
        const u32 sb = sbase + stage * STAGE_BYTES;
        #pragma unroll
        for (int ks = 0; ks < 4; ks++) {
            u32 a[2][4], b0f[2][4], b1f[2][4];
            #pragma unroll
            for (int mt = 0; mt < 2; mt++) {
                const int row = wm + mt * 16 + (lane & 15);
                const int cb  = ks * 32 + ((lane >> 4) * 16);
                ldm_x4(a[mt], sb + SWZ(row * 128 + cb));
            }
            {
                const int mi  = lane >> 3;
                const int rw  = wn + (mi >> 1) * 8 + (lane & 7);
                const int cb  = ks * 32 + (mi & 1) * 16;
                #pragma unroll
                for (int ntp = 0; ntp < 2; ntp++) {
                    ldm_x4(b0f[ntp], sb + 16384 +         SWZ((rw + ntp * 16) * 128 + cb));
                    ldm_x4(b1f[ntp], sb + 16384 + 16384 + SWZ((rw + ntp * 16) * 128 + cb));
                }
            }
            #pragma unroll
            for (int mt = 0; mt < 2; mt++)
                #pragma unroll
                for (int nt = 0; nt < 4; nt++)
                    mma16816(d[mt][nt], a[mt], b0f[nt >> 1][(nt & 1) * 2], b0f[nt >> 1][(nt & 1) * 2 + 1]);
            #pragma unroll
            for (int mt = 0; mt < 2; mt++)
                #pragma unroll
                for (int nt = 0; nt < 4; nt++)
                    mma16816(d[mt][nt], a[mt], b1f[nt >> 1][(nt & 1) * 2], b1f[nt >> 1][(nt & 1) * 2 + 1]);
            #pragma unroll
            for (int mt = 0; mt < 2; mt++) {
                const int row = wm + mt * 16 + (lane & 15);
                const int cb  = ks * 32 + ((lane >> 4) * 16);
                ldm_x4(a[mt], sb + 8192 + SWZ(row * 128 + cb));
            }
            #pragma unroll
            for (int mt = 0; mt < 2; mt++)
                #pragma unroll
                for (int nt = 0; nt < 4; nt++)
                    mma16816(d[mt][nt], a[mt], b0f[nt >> 1][(nt & 1) * 2], b0f[nt >> 1][(nt & 1) * 2 + 1]);
        }
    };

    load_chunk(0, 0);
    cp_commit();
    for (int c = 0; c < 8; c++) {
        if (c < 7) { load_chunk(c + 1, (c + 1) & 1); cp_commit(); cp_wait1(); }
        else       { cp_wait0(); }
        __syncthreads();
        compute_chunk(c & 1);
        __syncthreads();
    }

    if (transp == 0) {
        #pragma unroll
        for (int mt = 0; mt < 2; mt++) {
            const size_t mg = (size_t)(m0 + wm + mt * 16 + (lane >> 2));
            #pragma unroll
            for (int nt = 0; nt < 4; nt++) {
                const int n = n0 + wn + nt * 8 + (lane & 3) * 2;
                const float b0v = __ldg(&bias[n]), b1v = __ldg(&bias[n + 1]);
                float2 v0 = make_float2(d[mt][nt][0] + b0v, d[mt][nt][1] + b1v);
                float2 v1 = make_float2(d[mt][nt][2] + b0v, d[mt][nt][3] + b1v);
                *reinterpret_cast<float2*>(&out[mg * 512 + n])       = v0;
                *reinterpret_cast<float2*>(&out[(mg + 8) * 512 + n]) = v1;
            }
        }
    } else {
        float* S = reinterpret_cast<float*>(smem);
        const int RS = 68;                  // multiple of 4: float4-aligned rows
        #pragma unroll
        for (int mt = 0; mt < 2; mt++) {
            const int ml = wm + mt * 16 + (lane >> 2);
            #pragma unroll
            for (int nt = 0; nt < 4; nt++) {
                const int nl = wn + nt * 8 + (lane & 3) * 2;
                const float b0v = __ldg(&bias[n0 + nl]), b1v = __ldg(&bias[n0 + nl + 1]);
                S[nl * RS + ml]           = d[mt][nt][0] + b0v;
                S[(nl + 1) * RS + ml]     = d[mt][nt][1] + b1v;
                S[nl * RS + ml + 8]       = d[mt][nt][2] + b0v;
                S[(nl + 1) * RS + ml + 8] = d[mt][nt][3] + b1v;
            }
        }
        __syncthreads();
        const int bI = m0 >> 12;
        const int t0 = m0 & 4095;
        const int r    = tid >> 1;          // 0..127: local n row
        const int half = tid & 1;           // 32-float half along t
        float* dp = &out[((size_t)bI * 512 + n0 + r) * 4096 + t0 + half * 32];
        const float* sp = &S[r * RS + half * 32];
        #pragma unroll
        for (int u = 0; u < 8; u++)
            reinterpret_cast<float4*>(dp)[u] = reinterpret_cast<const float4*>(sp)[u];
    }
}

// Fused Q/K/V projections: blockIdx.z selects weight/bias/output/layout.
__global__ void __launch_bounds__(256, 2) gemm_qkv(
    const __nv_bfloat16* __restrict__ A0, const __nv_bfloat16* __restrict__ A1,
    const __nv_bfloat16* __restrict__ WS,
    const float* __restrict__ bq, const float* __restrict__ bk, const float* __restrict__ bv,
    float* __restrict__ Qt, float* __restrict__ Kt, float* __restrict__ V)
{
    extern __shared__ char smem[];
    const int z = blockIdx.z;
    const __nv_bfloat16* B0 = WS + (size_t)z * 2 * NWEL;
    const __nv_bfloat16* B1 = B0 + NWEL;
    const float* bias = (z == 0) ? bq : (z == 1) ? bk : bv;
    float* out        = (z == 0) ? Qt : (z == 1) ? Kt : V;
    gemm_body(A0, A1, B0, B1, bias, out, (z == 2) ? 0 : 1, smem);
}

// Single GEMM (output projection), channel-major out.
__global__ void __launch_bounds__(256, 2) gemm_single(
    const __nv_bfloat16* __restrict__ A0, const __nv_bfloat16* __restrict__ A1,
    const __nv_bfloat16* __restrict__ B0, const __nv_bfloat16* __restrict__ B1,
    const float* __restrict__ bias, float* __restrict__ out)
{
    extern __shared__ char smem[];
    gemm_body(A0, A1, B0, B1, bias, out, 0, smem);
}

// ---------------- radix-4 Stockham FFT, N=4096, 6 stages, 512 threads -------
__device__ __forceinline__ float2 cmul(float2 a, float2 w) {
    return make_float2(w.x * a.x - w.y * a.y, w.x * a.y + w.y * a.x);
}
__device__ void fft4096(float2* a, float2* b) {
    float2* src = a;
    float2* dst = b;
    #pragma unroll
    for (int s = 0; s < 6; s++) {
        const int Ns = 1 << (2 * s);
        const int sh = 10 - 2 * s;
        #pragma unroll
        for (int r = 0; r < 2; r++) {
            const int j = threadIdx.x + r * 512;
            float2 c0 = src[j];
            float2 c1 = src[j + 1024];
            float2 c2 = src[j + 2048];
            float2 c3 = src[j + 3072];
            const int jm = j & (Ns - 1);
            if (s > 0) {
                const float2 w1 = g_TW[(jm << sh) & 4095];
                const float2 w2 = g_TW[((2 * jm) << sh) & 4095];
                const float2 w3 = g_TW[((3 * jm) << sh) & 4095];
                c1 = cmul(c1, w1);
                c2 = cmul(c2, w2);
                c3 = cmul(c3, w3);
            }
            const float2 t0 = make_float2(c0.x + c2.x, c0.y + c2.y);
            const float2 t1 = make_float2(c0.x - c2.x, c0.y - c2.y);
            const float2 t2 = make_float2(c1.x + c3.x, c1.y + c3.y);
            const float2 t3 = make_float2(c1.x - c3.x, c1.y - c3.y);
            const float2 t3m = make_float2(t3.y, -t3.x);    // -i * t3
            const int idx = ((j >> (2 * s)) << (2 * s + 2)) | jm;
            dst[idx]          = make_float2(t0.x + t2.x, t0.y + t2.y);
            dst[idx + Ns]     = make_float2(t1.x + t3m.x, t1.y + t3m.y);
            dst[idx + 2 * Ns] = make_float2(t0.x - t2.x, t0.y - t2.y);
            dst[idx + 3 * Ns] = make_float2(t1.x - t3m.x, t1.y - t3m.y);
        }
        __syncthreads();
        float2* t = src; src = dst; dst = t;
    }
}

// ---------------- forward FFTs -> per-series partial spectra (no atomics) ----
__global__ void corr_fft_kernel(const float* __restrict__ Qt, const float* __restrict__ Kt,
                                float* __restrict__ PP)
{
    extern __shared__ float2 sm[];
    float2* bufA = sm;
    float2* bufB = sm + 4096;
    const int seq = blockIdx.x;          // b*512 + h*64 + d
    const float* q = Qt + (size_t)seq * 4096;
    const float* k = Kt + (size_t)seq * 4096;
    float* pp = PP + (size_t)seq * NF * 2;

    #pragma unroll
    for (int r = 0; r < 8; r++) {
        const int t = threadIdx.x + r * 512;
        bufA[t] = make_float2(q[t], k[t]);
    }
    __syncthreads();

    fft4096(bufA, bufB);

    for (int f = threadIdx.x; f <= 2048; f += 512) {
        const float2 Zf = bufA[f];
        const float2 Zm = bufA[(4096 - f) & 4095];
        const float qx = 0.5f * (Zf.x + Zm.x);
        const float qy = 0.5f * (Zf.y - Zm.y);
        const float kx = 0.5f * (Zf.y + Zm.y);
        const float ky = -0.5f * (Zf.x - Zm.x);
        pp[f * 2]     = qx * kx + qy * ky;
        pp[f * 2 + 1] = qy * kx - qx * ky;
    }
}

// ---------------- sum partials over d: FS[bh][f] = sum_d PP[bh*64+d][f] -----
__global__ void sum_fs_kernel(const float* __restrict__ PP, float* __restrict__ FS)
{
    const int bh = blockIdx.x;
    const int f  = blockIdx.y * 256 + threadIdx.x;
    if (f > 2048) return;
    const float* base = PP + ((size_t)bh * 64) * NF * 2 + f * 2;
    float sx = 0.0f, sy = 0.0f;
    #pragma unroll 8
    for (int d = 0; d < 64; d++) {
        sx += base[(size_t)d * NF * 2];
        sy += base[(size_t)d * NF * 2 + 1];
    }
    FS[(bh * NF + f) * 2]     = sx;
    FS[(bh * NF + f) * 2 + 1] = sy;
}

// ---------------- inverse FFT + top-k + softmax (shuffle reductions) --------
__global__ void reduce_topk_kernel(const float* __restrict__ FS,
                                   float* __restrict__ WGT, int* __restrict__ DLY)
{
    extern __shared__ float2 sm[];
    float2* bufA = sm;
    float2* bufB = sm + 4096;
    __shared__ float wv[16];
    __shared__ int   wi[16];
    __shared__ float topv[KTOP];
    __shared__ int   topi[KTOP];

    const int bh = blockIdx.x;
    const int tid = threadIdx.x;
    const int lane = tid & 31;
    const int wrp  = tid >> 5;

    for (int f = tid; f < 4096; f += 512) {
        float2 v;
        if (f <= 2048) {
            v.x =  FS[(bh * NF + f) * 2];
            v.y = -FS[(bh * NF + f) * 2 + 1];
        } else {
            const int fm = 4096 - f;
            v.x = FS[(bh * NF + fm) * 2];
            v.y = FS[(bh * NF + fm) * 2 + 1];
        }
        bufA[f] = v;
    }
    __syncthreads();

    fft4096(bufA, bufB);

    float* cbuf = reinterpret_cast<float*>(bufB);
    const float scale = 1.0f / (4096.0f * 64.0f);
    for (int t = tid; t < 4096; t += 512) cbuf[t] = bufA[t].x * scale;
    __syncthreads();

    for (int it = 0; it < KTOP; it++) {
        float best = -1e30f; int bi = 0;
        #pragma unroll
        for (int r = 0; r < 8; r++) {
            const int t = tid + r * 512;
            const float v = cbuf[t];
            if (v > best || (v == best && t < bi)) { best = v; bi = t; }
        }
        #pragma unroll
        for (int off = 16; off > 0; off >>= 1) {
            const float ov = __shfl_xor_sync(0xFFFFFFFF, best, off);
            const int   oi = __shfl_xor_sync(0xFFFFFFFF, bi,   off);
            if (ov > best || (ov == best && oi < bi)) { best = ov; bi = oi; }
        }
        if (lane == 0) { wv[wrp] = best; wi[wrp] = bi; }
        __syncthreads();
        if (wrp == 0) {
            float v2 = (lane < 16) ? wv[lane] : -1e30f;
            int   i2 = (lane < 16) ? wi[lane] : 0;
            #pragma unroll
            for (int off = 8; off > 0; off >>= 1) {
                const float ov = __shfl_xor_sync(0xFFFFFFFF, v2, off);
                const int   oi = __shfl_xor_sync(0xFFFFFFFF, i2, off);
                if (ov > v2 || (ov == v2 && oi < i2)) { v2 = ov; i2 = oi; }
            }
            if (lane == 0) {
                topv[it] = v2; topi[it] = i2;
                cbuf[i2] = -1e30f;
            }
        }
        __syncthreads();
    }

    if (tid == 0) {
        float m = topv[0];
        #pragma unroll
        for (int j = 1; j < KTOP; j++) m = fmaxf(m, topv[j]);
        float e[KTOP]; float s = 0.0f;
        #pragma unroll
        for (int j = 0; j < KTOP; j++) { e[j] = expf(topv[j] - m); s += e[j]; }
        const float inv = 1.0f / s;
        #pragma unroll
        for (int j = 0; j < KTOP; j++) {
            WGT[bh * KTOP + j] = e[j] * inv;
            DLY[bh * KTOP + j] = topi[j];
        }
    }
}

// ---------------- delay gather: writes bf16 limb pair directly --------------
__global__ void __launch_bounds__(256) gather_kernel(
    const float* __restrict__ V, const float* __restrict__ WGT,
    const int* __restrict__ DLY,
    __nv_bfloat16* __restrict__ C0, __nv_bfloat16* __restrict__ C1)
{
    __shared__ float w[128];
    __shared__ int   dl[128];
    const int blk = blockIdx.x;
    const int b  = blk >> 10;
    const int t0 = (blk & 1023) * 4;
    const int tid = threadIdx.x;

    if (tid < 128) {
        const int h = tid >> 4, j = tid & 15;
        w[tid]  = WGT[(b * 8 + h) * KTOP + j];
        dl[tid] = DLY[(b * 8 + h) * KTOP + j];
    }
    __syncthreads();

    const int c2 = tid;                 // float2 channel index 0..255
    const int h  = c2 >> 5;
    const float* wp = &w[h * 16];
    const int*   dp = &dl[h * 16];
    const float2* Vb = reinterpret_cast<const float2*>(V + (size_t)b * 4096 * 512);

    #pragma unroll
    for (int tt = 0; tt < 4; tt++) {
        const int t = t0 + tt;
        float ax = 0.0f, ay = 0.0f;
        #pragma unroll
        for (int j = 0; j < 16; j++) {
            const int idx = (t - dp[j]) & 4095;
            const float2 v = Vb[(size_t)idx * 256 + c2];
            ax += wp[j] * v.x;
            ay += wp[j] * v.y;
        }
        const __nv_bfloat16 x0 = __float2bfloat16(ax);
        const __nv_bfloat16 x1 = __float2bfloat16(ax - __bfloat162float(x0));
        const __nv_bfloat16 y0 = __float2bfloat16(ay);
        const __nv_bfloat16 y1 = __float2bfloat16(ay - __bfloat162float(y0));
        const size_t oi = ((size_t)b * 4096 + t) * 256 + c2;
        reinterpret_cast<u32*>(C0)[oi] =
            (u32)__bfloat16_as_ushort(x0) | ((u32)__bfloat16_as_ushort(y0) << 16);
        reinterpret_cast<u32*>(C1)[oi] =
            (u32)__bfloat16_as_ushort(x1) | ((u32)__bfloat16_as_ushort(y1) << 16);
    }
}

// ---------------- host entry ----------------
extern "C" void kernel_launch(void* const* d_in, const int* in_sizes, int n_in,
                              void* d_out, int out_size)
{
    const float* x  = (const float*)d_in[0];
    const float* Wq = (const float*)d_in[1];
    const float* bq = (const float*)d_in[2];
    const float* Wk = (const float*)d_in[3];
    const float* bk = (const float*)d_in[4];
    const float* Wv = (const float*)d_in[5];
    const float* bv = (const float*)d_in[6];
    const float* Wo = (const float*)d_in[7];
    const float* bo = (const float*)d_in[8];
    float* out = (float*)d_out;

    float *Qt, *Kt, *V, *PP, *FS, *WGT; int* DLY;
    __nv_bfloat16 *XS, *CS, *WS;
    cudaGetSymbolAddress((void**)&Qt,  g_Qt);
    cudaGetSymbolAddress((void**)&Kt,  g_Kt);
    cudaGetSymbolAddress((void**)&V,   g_V);
    cudaGetSymbolAddress((void**)&PP,  g_PP);
    cudaGetSymbolAddress((void**)&FS,  g_FS);
    cudaGetSymbolAddress((void**)&WGT, g_W);
    cudaGetSymbolAddress((void**)&DLY, g_D);
    cudaGetSymbolAddress((void**)&XS,  g_XS);
    cudaGetSymbolAddress((void**)&CS,  g_CS);
    cudaGetSymbolAddress((void**)&WS,  g_WS);

    const size_t NX = (size_t)MTOT * DM_;     // 8388608
    __nv_bfloat16* XSp[2] = {XS, XS + NX};
    __nv_bfloat16* CSp[2] = {CS, CS + NX};
    __nv_bfloat16* WOp0 = WS + (size_t)3 * 2 * NWEL;
    __nv_bfloat16* WOp1 = WOp0 + NWEL;

    const int SMEM = 2 * STAGE_BYTES;   // 98304 per CTA -> 2 CTAs/SM
    cudaFuncSetAttribute(gemm_qkv,    cudaFuncAttributeMaxDynamicSharedMemorySize, SMEM);
    cudaFuncSetAttribute(gemm_single, cudaFuncAttributeMaxDynamicSharedMemorySize, SMEM);
    cudaFuncSetAttribute(corr_fft_kernel,    cudaFuncAttributeMaxDynamicSharedMemorySize, 65536);
    cudaFuncSetAttribute(reduce_topk_kernel, cudaFuncAttributeMaxDynamicSharedMemorySize, 65536);

    // launch order: ncu captures launch #4 -> corr_fft there this round
    convert_all_kernel<<<9216, 256>>>(x, Wq, Wk, Wv, Wo, XSp[0], XSp[1], WS);               // 1
    setup_kernel<<<16, 256>>>();                                                             // 2
    gemm_qkv<<<dim3(256, 4, 3), 256, SMEM>>>(XSp[0], XSp[1], WS, bq, bk, bv, Qt, Kt, V);     // 3
    corr_fft_kernel<<<NSEQ, 512, 65536>>>(Qt, Kt, PP);                                       // 4 <- profiled
    sum_fs_kernel<<<dim3(NBH, 9), 256>>>(PP, FS);                                            // 5
    reduce_topk_kernel<<<NBH, 512, 65536>>>(FS, WGT, DLY);                                   // 6
    gather_kernel<<<B_ * (L_ / 4), 256>>>(V, WGT, DLY, CSp[0], CSp[1]);                      // 7
    gemm_single<<<dim3(256, 4, 1), 256, SMEM>>>(CSp[0], CSp[1], WOp0, WOp1, bo, out);        // 8
}

// round 13
// speedup vs baseline: 1.0224x; 1.0224x over previous
#include <cuda_runtime.h>
#include <cuda_bf16.h>
#include <math.h>
#include <cstdint>

// ---------------- problem constants ----------------
#define B_  4
#define L_  4096
#define DM_ 512
#define KTOP 16
#define NBH 32            // B*H
#define NF 2049           // L/2+1
#define MTOT (B_*L_)      // 16384
#define NSEQ (B_*DM_)     // 2048 FFT series
#define NWEL (DM_*DM_)    // 262144 weight elements

typedef unsigned long long u64;
typedef unsigned int u32;

// ---------------- scratch (static __device__, no allocation) ----------------
__device__ float g_Qt[(size_t)B_*DM_*L_];    // Q time-major [(b*512+n)*4096+t]
__device__ float g_Kt[(size_t)B_*DM_*L_];    // K time-major
__device__ float g_V [(size_t)MTOT*DM_];     // V channel-major
__device__ float g_PP[(size_t)NSEQ*NF*2];    // per-series partial cross-spectra
__device__ float g_FS[NBH*NF*2];             // summed cross-spectrum
__device__ float g_W [NBH*KTOP];
__device__ int   g_D [NBH*KTOP];
__device__ float2 g_TW[4096];                // FFT twiddles exp(-2πik/4096)
__device__ __nv_bfloat16 g_XS[2][(size_t)MTOT*DM_];   // x split limbs
__device__ __nv_bfloat16 g_CS[2][(size_t)MTOT*DM_];   // ctx split limbs (gather output)
__device__ __nv_bfloat16 g_WS[4][2][NWEL];            // Wq,Wk,Wv,Wo split limbs

// ---------------- helpers ----------------
__device__ __forceinline__ u32 smem_u32(const void* p) {
    u32 a;
    asm("{ .reg .u64 t; cvta.to.shared.u64 t, %1; cvt.u32.u64 %0, t; }" : "=r"(a) : "l"(p));
    return a;
}
#define SWZ(x) ((u32)(x) ^ ((((u32)(x)) >> 3) & 0x70))

__device__ __forceinline__ void cp16(u32 dst, const void* src) {
    asm volatile("cp.async.cg.shared.global [%0], [%1], 16;" :: "r"(dst), "l"(src));
}
__device__ __forceinline__ void cp_commit() {
    asm volatile("cp.async.commit_group;" ::: "memory");
}
__device__ __forceinline__ void cp_wait1() {
    asm volatile("cp.async.wait_group 1;" ::: "memory");
}
__device__ __forceinline__ void cp_wait0() {
    asm volatile("cp.async.wait_group 0;" ::: "memory");
}
__device__ __forceinline__ void ldm_x4(u32* r, u32 addr) {
    asm volatile("ldmatrix.sync.aligned.m8n8.x4.shared.b16 {%0,%1,%2,%3}, [%4];"
        : "=r"(r[0]), "=r"(r[1]), "=r"(r[2]), "=r"(r[3]) : "r"(addr));
}
__device__ __forceinline__ void mma16816(float* d, const u32* a, u32 b0, u32 b1) {
    asm volatile(
        "mma.sync.aligned.m16n8k16.row.col.f32.bf16.bf16.f32 "
        "{%0,%1,%2,%3}, {%4,%5,%6,%7}, {%8,%9}, {%0,%1,%2,%3};"
        : "+f"(d[0]), "+f"(d[1]), "+f"(d[2]), "+f"(d[3])
        : "r"(a[0]), "r"(a[1]), "r"(a[2]), "r"(a[3]), "r"(b0), "r"(b1));
}

// ---------------- fused limb-split converts: x (8192 blocks) + 4 W (1024) ---
__global__ void convert_all_kernel(const float* __restrict__ x,
    const float* __restrict__ Wq, const float* __restrict__ Wk,
    const float* __restrict__ Wv, const float* __restrict__ Wo,
    __nv_bfloat16* __restrict__ XS0, __nv_bfloat16* __restrict__ XS1,
    __nv_bfloat16* __restrict__ WS)
{
    const float* src;
    __nv_bfloat16 *d0, *d1;
    int i;
    if (blockIdx.x < 8192) {
        src = x; d0 = XS0; d1 = XS1;
        i = blockIdx.x * 256 + threadIdx.x;
    } else {
        const int wblk = blockIdx.x - 8192;
        const int w = wblk >> 8;
        src = (w == 0) ? Wq : (w == 1) ? Wk : (w == 2) ? Wv : Wo;
        d0 = WS + (size_t)w * 2 * NWEL;
        d1 = d0 + NWEL;
        i = (wblk & 255) * 256 + threadIdx.x;
    }
    const float4 v = reinterpret_cast<const float4*>(src)[i];
    const float f[4] = {v.x, v.y, v.z, v.w};
    unsigned short h0[4], h1[4];
    #pragma unroll
    for (int j = 0; j < 4; j++) {
        __nv_bfloat16 b0 = __float2bfloat16(f[j]);
        float r = f[j] - __bfloat162float(b0);
        __nv_bfloat16 b1 = __float2bfloat16(r);
        h0[j] = __bfloat16_as_ushort(b0);
        h1[j] = __bfloat16_as_ushort(b1);
    }
    reinterpret_cast<uint2*>(d0)[i] = make_uint2((u32)h0[0] | ((u32)h0[1] << 16), (u32)h0[2] | ((u32)h0[3] << 16));
    reinterpret_cast<uint2*>(d1)[i] = make_uint2((u32)h1[0] | ((u32)h1[1] << 16), (u32)h1[2] | ((u32)h1[3] << 16));
}

// ---------------- setup: twiddles ----------------
__global__ void setup_kernel() {
    const int i = blockIdx.x * blockDim.x + threadIdx.x;
    if (i < 4096) {
        const double ang = -6.283185307179586476925 * (double)i / 4096.0;
        g_TW[i] = make_float2((float)cos(ang), (float)sin(ang));
    }
}

// ---------------- mma.sync split-bf16 GEMM body (3-term: 00,01,10) ----------
// CTA tile 64x128, 256 threads (2x4 warps, 32x32 warp tiles), k-chunk 64.
// Stage 48KB, double-buffered -> 96KB/CTA => 2 CTAs resident per SM.
#define STAGE_BYTES 49152     // A: 2 limbs x 8KB, B: 2 limbs x 16KB
__device__ __forceinline__ void gemm_body(
    const __nv_bfloat16* __restrict__ A0, const __nv_bfloat16* __restrict__ A1,
    const __nv_bfloat16* __restrict__ B0, const __nv_bfloat16* __restrict__ B1,
    const float* __restrict__ bias, float* __restrict__ out,
    const int transp, char* smem)
{
    const u32 sbase = smem_u32(smem);

    const int tid  = threadIdx.x;
    const int wid  = tid >> 5;
    const int lane = tid & 31;
    const int wm   = (wid & 1) * 32;     // warp m offset
    const int wn   = (wid >> 1) * 32;    // warp n offset
    const int m0   = blockIdx.x * 64;
    const int n0   = blockIdx.y * 128;

    const __nv_bfloat16* Ap[2] = {A0, A1};
    const __nv_bfloat16* Bp[2] = {B0, B1};

    float d[2][4][4];
    #pragma unroll
    for (int i = 0; i < 2; i++)
        #pragma unroll
        for (int j = 0; j < 4; j++)
            #pragma unroll
            for (int q = 0; q < 4; q++) d[i][j][q] = 0.0f;

    auto load_chunk = [&](int c, int stage) {
        const int k0 = c * 64;
        const u32 sb = sbase + stage * STAGE_BYTES;
        #pragma unroll
        for (int t = 0; t < 2; t++) {
            const char* gA = reinterpret_cast<const char*>(Ap[t]) + ((size_t)m0 * 512 + k0) * 2;
            const u32 sA = sb + t * 8192;
            #pragma unroll
            for (int i = 0; i < 2; i++) {            // 512 16B units (64 rows)
                const int u = tid + i * 256;
                const int row = u >> 3, cu = u & 7;
                cp16(sA + SWZ(row * 128 + cu * 16), gA + (size_t)row * 1024 + cu * 16);
            }
            const char* gB = reinterpret_cast<const char*>(Bp[t]) + ((size_t)n0 * 512 + k0) * 2;
            const u32 sB = sb + 16384 + t * 16384;
            #pragma unroll
            for (int i = 0; i < 4; i++) {            // 1024 16B units (128 rows)
                const int u = tid + i * 256;
                const int row = u >> 3, cu = u & 7;
                cp16(sB + SWZ(row * 128 + cu * 16), gB + (size_t)row * 1024 + cu * 16);
            }
        }
    };

    auto compute_chunk = [&](int stage) {
        const u32 sb = sbase + stage * STAGE_BYTES;
        #pragma unroll
        for (int ks = 0; ks < 4; ks++) {
            u32 a[2][4], b0f[2][4], b1f[2][4];
            #pragma unroll
            for (int mt = 0; mt < 2; mt++) {
                const int row = wm + mt * 16 + (lane & 15);
                const int cb  = ks * 32 + ((lane >> 4) * 16);
                ldm_x4(a[mt], sb + SWZ(row * 128 + cb));
            }
            {
                const int mi  = lane >> 3;
                const int rw  = wn + (mi >> 1) * 8 + (lane & 7);
                const int cb  = ks * 32 + (mi & 1) * 16;
                #pragma unroll
                for (int ntp = 0; ntp < 2; ntp++) {
                    ldm_x4(b0f[ntp], sb + 16384 +         SWZ((rw + ntp * 16) * 128 + cb));
                    ldm_x4(b1f[ntp], sb + 16384 + 16384 + SWZ((rw + ntp * 16) * 128 + cb));
                }
            }
            #pragma unroll
            for (int mt = 0; mt < 2; mt++)
                #pragma unroll
                for (int nt = 0; nt < 4; nt++)
                    mma16816(d[mt][nt], a[mt], b0f[nt >> 1][(nt & 1) * 2], b0f[nt >> 1][(nt & 1) * 2 + 1]);
            #pragma unroll
            for (int mt = 0; mt < 2; mt++)
                #pragma unroll
                for (int nt = 0; nt < 4; nt++)
                    mma16816(d[mt][nt], a[mt], b1f[nt >> 1][(nt & 1) * 2], b1f[nt >> 1][(nt & 1) * 2 + 1]);
            #pragma unroll
            for (int mt = 0; mt < 2; mt++) {
                const int row = wm + mt * 16 + (lane & 15);
                const int cb  = ks * 32 + ((lane >> 4) * 16);
                ldm_x4(a[mt], sb + 8192 + SWZ(row * 128 + cb));
            }
            #pragma unroll
            for (int mt = 0; mt < 2; mt++)
                #pragma unroll
                for (int nt = 0; nt < 4; nt++)
                    mma16816(d[mt][nt], a[mt], b0f[nt >> 1][(nt & 1) * 2], b0f[nt >> 1][(nt & 1) * 2 + 1]);
        }
    };

    load_chunk(0, 0);
    cp_commit();
    for (int c = 0; c < 8; c++) {
        if (c < 7) { load_chunk(c + 1, (c + 1) & 1); cp_commit(); cp_wait1(); }
        else       { cp_wait0(); }
        __syncthreads();
        compute_chunk(c & 1);
        __syncthreads();
    }

    if (transp == 0) {
        #pragma unroll
        for (int mt = 0; mt < 2; mt++) {
            const size_t mg = (size_t)(m0 + wm + mt * 16 + (lane >> 2));
            #pragma unroll
            for (int nt = 0; nt < 4; nt++) {
                const int n = n0 + wn + nt * 8 + (lane & 3) * 2;
                const float b0v = __ldg(&bias[n]), b1v = __ldg(&bias[n + 1]);
                float2 v0 = make_float2(d[mt][nt][0] + b0v, d[mt][nt][1] + b1v);
                float2 v1 = make_float2(d[mt][nt][2] + b0v, d[mt][nt][3] + b1v);
                *reinterpret_cast<float2*>(&out[mg * 512 + n])       = v0;
                *reinterpret_cast<float2*>(&out[(mg + 8) * 512 + n]) = v1;
            }
        }
    } else {
        float* S = reinterpret_cast<float*>(smem);
        const int RS = 68;                  // multiple of 4: float4-aligned rows
        #pragma unroll
        for (int mt = 0; mt < 2; mt++) {
            const int ml = wm + mt * 16 + (lane >> 2);
            #pragma unroll
            for (int nt = 0; nt < 4; nt++) {
                const int nl = wn + nt * 8 + (lane & 3) * 2;
                const float b0v = __ldg(&bias[n0 + nl]), b1v = __ldg(&bias[n0 + nl + 1]);
                S[nl * RS + ml]           = d[mt][nt][0] + b0v;
                S[(nl + 1) * RS + ml]     = d[mt][nt][1] + b1v;
                S[nl * RS + ml + 8]       = d[mt][nt][2] + b0v;
                S[(nl + 1) * RS + ml + 8] = d[mt][nt][3] + b1v;
            }
        }
        __syncthreads();
        const int bI = m0 >> 12;
        const int t0 = m0 & 4095;
        const int r    = tid >> 1;          // 0..127: local n row
        const int half = tid & 1;           // 32-float half along t
        float* dp = &out[((size_t)bI * 512 + n0 + r) * 4096 + t0 + half * 32];
        const float* sp = &S[r * RS + half * 32];
        #pragma unroll
        for (int u = 0; u < 8; u++)
            reinterpret_cast<float4*>(dp)[u] = reinterpret_cast<const float4*>(sp)[u];
    }
}

// Fused Q/K/V projections: blockIdx.z selects weight/bias/output/layout.
__global__ void __launch_bounds__(256, 2) gemm_qkv(
    const __nv_bfloat16* __restrict__ A0, const __nv_bfloat16* __restrict__ A1,
    const __nv_bfloat16* __restrict__ WS,
    const float* __restrict__ bq, const float* __restrict__ bk, const float* __restrict__ bv,
    float* __restrict__ Qt, float* __restrict__ Kt, float* __restrict__ V)
{
    extern __shared__ char smem[];
    const int z = blockIdx.z;
    const __nv_bfloat16* B0 = WS + (size_t)z * 2 * NWEL;
    const __nv_bfloat16* B1 = B0 + NWEL;
    const float* bias = (z == 0) ? bq : (z == 1) ? bk : bv;
    float* out        = (z == 0) ? Qt : (z == 1) ? Kt : V;
    gemm_body(A0, A1, B0, B1, bias, out, (z == 2) ? 0 : 1, smem);
}

// Single GEMM (output projection), channel-major out.
__global__ void __launch_bounds__(256, 2) gemm_single(
    const __nv_bfloat16* __restrict__ A0, const __nv_bfloat16* __restrict__ A1,
    const __nv_bfloat16* __restrict__ B0, const __nv_bfloat16* __restrict__ B1,
    const float* __restrict__ bias, float* __restrict__ out)
{
    extern __shared__ char smem[];
    gemm_body(A0, A1, B0, B1, bias, out, 0, smem);
}

// ---------------- radix-8 Stockham FFT, N=4096, 4 stages, 512 threads -------
// Bank-rotation swizzles kill the stage-0 (8-way) and stage-1 (2-way) store
// conflicts; the consuming stage applies the same bijective map on its reads.
__device__ __forceinline__ float2 cmul(float2 a, float2 w) {
    return make_float2(w.x * a.x - w.y * a.y, w.x * a.y + w.y * a.x);
}
__device__ __forceinline__ float2 cadd(float2 a, float2 b) { return make_float2(a.x + b.x, a.y + b.y); }
__device__ __forceinline__ float2 csub(float2 a, float2 b) { return make_float2(a.x - b.x, a.y - b.y); }
__device__ __forceinline__ int phys0(int p) {
    return (p & ~7) | (((p & 7) + (p >> 3)) & 7);
}
__device__ __forceinline__ int phys1(int p) {
    return (p & ~63) | (p & 7) | (((((p >> 3) & 7) + (p >> 6)) & 7) << 3);
}

__device__ __forceinline__ void bfly8(float2* c) {
    const float SQ = 0.70710678118654752f;
    float2 t0 = cadd(c[0], c[4]), t1 = csub(c[0], c[4]);
    float2 t2 = cadd(c[2], c[6]), t3 = csub(c[2], c[6]);
    float2 t3m = make_float2(t3.y, -t3.x);
    float2 E0 = cadd(t0, t2), E1 = cadd(t1, t3m), E2 = csub(t0, t2), E3 = csub(t1, t3m);
    float2 u0 = cadd(c[1], c[5]), u1 = csub(c[1], c[5]);
    float2 u2 = cadd(c[3], c[7]), u3 = csub(c[3], c[7]);
    float2 u3m = make_float2(u3.y, -u3.x);
    float2 O0 = cadd(u0, u2), O1 = cadd(u1, u3m), O2 = csub(u0, u2), O3 = csub(u1, u3m);
    float2 W1 = make_float2(SQ * (O1.x + O1.y), SQ * (O1.y - O1.x));
    float2 W2 = make_float2(O2.y, -O2.x);
    float2 W3 = make_float2(SQ * (O3.y - O3.x), -SQ * (O3.x + O3.y));
    c[0] = cadd(E0, O0); c[4] = csub(E0, O0);
    c[1] = cadd(E1, W1); c[5] = csub(E1, W1);
    c[2] = cadd(E2, W2); c[6] = csub(E2, W2);
    c[3] = cadd(E3, W3); c[7] = csub(E3, W3);
}

__device__ void fft4096(float2* A, float2* Bb) {
    const int j = threadIdx.x;
    float2 c[8];

    // stage 0: Ns=1 (no twiddle); read natural A, write phys0 -> B
    #pragma unroll
    for (int q = 0; q < 8; q++) c[q] = A[j + q * 512];
    bfly8(c);
    {
        const int base = j << 3;
        #pragma unroll
        for (int r = 0; r < 8; r++) Bb[phys0(base + r)] = c[r];
    }
    __syncthreads();

    // stage 1: Ns=8, sh=6; read phys0 B, write phys1 -> A
    {
        const int jm = j & 7;
        #pragma unroll
        for (int q = 0; q < 8; q++) c[q] = Bb[phys0(j + q * 512)];
        #pragma unroll
        for (int q = 1; q < 8; q++) c[q] = cmul(c[q], g_TW[(q * jm << 6) & 4095]);
        bfly8(c);
        const int base = ((j >> 3) << 6) | jm;
        #pragma unroll
        for (int r = 0; r < 8; r++) A[phys1(base + (r << 3))] = c[r];
    }
    __syncthreads();

    // stage 2: Ns=64, sh=3; read phys1 A, write natural -> B
    {
        const int jm = j & 63;
        #pragma unroll
        for (int q = 0; q < 8; q++) c[q] = A[phys1(j + q * 512)];
        #pragma unroll
        for (int q = 1; q < 8; q++) c[q] = cmul(c[q], g_TW[(q * jm << 3) & 4095]);
        bfly8(c);
        const int base = ((j >> 6) << 9) | jm;
        #pragma unroll
        for (int r = 0; r < 8; r++) Bb[base + (r << 6)] = c[r];
    }
    __syncthreads();

    // stage 3: Ns=512, sh=0; read natural B, write natural -> A
    {
        #pragma unroll
        for (int q = 0; q < 8; q++) c[q] = Bb[j + q * 512];
        #pragma unroll
        for (int q = 1; q < 8; q++) c[q] = cmul(c[q], g_TW[(q * j) & 4095]);
        bfly8(c);
        #pragma unroll
        for (int r = 0; r < 8; r++) A[j + (r << 9)] = c[r];
    }
    __syncthreads();
}

// ---------------- forward FFTs -> per-series partial spectra (no atomics) ----
__global__ void corr_fft_kernel(const float* __restrict__ Qt, const float* __restrict__ Kt,
                                float* __restrict__ PP)
{
    extern __shared__ float2 sm[];
    float2* bufA = sm;
    float2* bufB = sm + 4096;
    const int seq = blockIdx.x;          // b*512 + h*64 + d
    const float* q = Qt + (size_t)seq * 4096;
    const float* k = Kt + (size_t)seq * 4096;
    float* pp = PP + (size_t)seq * NF * 2;

    #pragma unroll
    for (int r = 0; r < 8; r++) {
        const int t = threadIdx.x + r * 512;
        bufA[t] = make_float2(q[t], k[t]);
    }
    __syncthreads();

    fft4096(bufA, bufB);

    for (int f = threadIdx.x; f <= 2048; f += 512) {
        const float2 Zf = bufA[f];
        const float2 Zm = bufA[(4096 - f) & 4095];
        const float qx = 0.5f * (Zf.x + Zm.x);
        const float qy = 0.5f * (Zf.y - Zm.y);
        const float kx = 0.5f * (Zf.y + Zm.y);
        const float ky = -0.5f * (Zf.x - Zm.x);
        pp[f * 2]     = qx * kx + qy * ky;
        pp[f * 2 + 1] = qy * kx - qx * ky;
    }
}

// ---------------- sum partials over d: FS[bh][f] = sum_d PP[bh*64+d][f] -----
__global__ void sum_fs_kernel(const float* __restrict__ PP, float* __restrict__ FS)
{
    const int bh = blockIdx.x;
    const int f  = blockIdx.y * 256 + threadIdx.x;
    if (f > 2048) return;
    const float* base = PP + ((size_t)bh * 64) * NF * 2 + f * 2;
    float sx = 0.0f, sy = 0.0f;
    #pragma unroll 8
    for (int d = 0; d < 64; d++) {
        sx += base[(size_t)d * NF * 2];
        sy += base[(size_t)d * NF * 2 + 1];
    }
    FS[(bh * NF + f) * 2]     = sx;
    FS[(bh * NF + f) * 2 + 1] = sy;
}

// ---------------- inverse FFT + top-k + softmax (shuffle reductions) --------
__global__ void reduce_topk_kernel(const float* __restrict__ FS,
                                   float* __restrict__ WGT, int* __restrict__ DLY)
{
    extern __shared__ float2 sm[];
    float2* bufA = sm;
    float2* bufB = sm + 4096;
    __shared__ float wv[16];
    __shared__ int   wi[16];
    __shared__ float topv[KTOP];
    __shared__ int   topi[KTOP];

    const int bh = blockIdx.x;
    const int tid = threadIdx.x;
    const int lane = tid & 31;
    const int wrp  = tid >> 5;

    for (int f = tid; f < 4096; f += 512) {
        float2 v;
        if (f <= 2048) {
            v.x =  FS[(bh * NF + f) * 2];
            v.y = -FS[(bh * NF + f) * 2 + 1];
        } else {
            const int fm = 4096 - f;
            v.x = FS[(bh * NF + fm) * 2];
            v.y = FS[(bh * NF + fm) * 2 + 1];
        }
        bufA[f] = v;
    }
    __syncthreads();

    fft4096(bufA, bufB);

    float* cbuf = reinterpret_cast<float*>(bufB);
    const float scale = 1.0f / (4096.0f * 64.0f);
    for (int t = tid; t < 4096; t += 512) cbuf[t] = bufA[t].x * scale;
    __syncthreads();

    for (int it = 0; it < KTOP; it++) {
        float best = -1e30f; int bi = 0;
        #pragma unroll
        for (int r = 0; r < 8; r++) {
            const int t = tid + r * 512;
            const float v = cbuf[t];
            if (v > best || (v == best && t < bi)) { best = v; bi = t; }
        }
        #pragma unroll
        for (int off = 16; off > 0; off >>= 1) {
            const float ov = __shfl_xor_sync(0xFFFFFFFF, best, off);
            const int   oi = __shfl_xor_sync(0xFFFFFFFF, bi,   off);
            if (ov > best || (ov == best && oi < bi)) { best = ov; bi = oi; }
        }
        if (lane == 0) { wv[wrp] = best; wi[wrp] = bi; }
        __syncthreads();
        if (wrp == 0) {
            float v2 = (lane < 16) ? wv[lane] : -1e30f;
            int   i2 = (lane < 16) ? wi[lane] : 0;
            #pragma unroll
            for (int off = 8; off > 0; off >>= 1) {
                const float ov = __shfl_xor_sync(0xFFFFFFFF, v2, off);
                const int   oi = __shfl_xor_sync(0xFFFFFFFF, i2, off);
                if (ov > v2 || (ov == v2 && oi < i2)) { v2 = ov; i2 = oi; }
            }
            if (lane == 0) {
                topv[it] = v2; topi[it] = i2;
                cbuf[i2] = -1e30f;
            }
        }
        __syncthreads();
    }

    if (tid == 0) {
        float m = topv[0];
        #pragma unroll
        for (int j = 1; j < KTOP; j++) m = fmaxf(m, topv[j]);
        float e[KTOP]; float s = 0.0f;
        #pragma unroll
        for (int j = 0; j < KTOP; j++) { e[j] = expf(topv[j] - m); s += e[j]; }
        const float inv = 1.0f / s;
        #pragma unroll
        for (int j = 0; j < KTOP; j++) {
            WGT[bh * KTOP + j] = e[j] * inv;
            DLY[bh * KTOP + j] = topi[j];
        }
    }
}

// ---------------- delay gather: writes bf16 limb pair directly --------------
__global__ void __launch_bounds__(256) gather_kernel(
    const float* __restrict__ V, const float* __restrict__ WGT,
    const int* __restrict__ DLY,
    __nv_bfloat16* __restrict__ C0, __nv_bfloat16* __restrict__ C1)
{
    __shared__ float w[128];
    __shared__ int   dl[128];
    const int blk = blockIdx.x;
    const int b  = blk >> 10;
    const int t0 = (blk & 1023) * 4;
    const int tid = threadIdx.x;

    if (tid < 128) {
        const int h = tid >> 4, j = tid & 15;
        w[tid]  = WGT[(b * 8 + h) * KTOP + j];
        dl[tid] = DLY[(b * 8 + h) * KTOP + j];
    }
    __syncthreads();

    const int c2 = tid;                 // float2 channel index 0..255
    const int h  = c2 >> 5;
    const float* wp = &w[h * 16];
    const int*   dp = &dl[h * 16];
    const float2* Vb = reinterpret_cast<const float2*>(V + (size_t)b * 4096 * 512);

    #pragma unroll
    for (int tt = 0; tt < 4; tt++) {
        const int t = t0 + tt;
        float ax = 0.0f, ay = 0.0f;
        #pragma unroll
        for (int j = 0; j < 16; j++) {
            const int idx = (t - dp[j]) & 4095;
            const float2 v = Vb[(size_t)idx * 256 + c2];
            ax += wp[j] * v.x;
            ay += wp[j] * v.y;
        }
        const __nv_bfloat16 x0 = __float2bfloat16(ax);
        const __nv_bfloat16 x1 = __float2bfloat16(ax - __bfloat162float(x0));
        const __nv_bfloat16 y0 = __float2bfloat16(ay);
        const __nv_bfloat16 y1 = __float2bfloat16(ay - __bfloat162float(y0));
        const size_t oi = ((size_t)b * 4096 + t) * 256 + c2;
        reinterpret_cast<u32*>(C0)[oi] =
            (u32)__bfloat16_as_ushort(x0) | ((u32)__bfloat16_as_ushort(y0) << 16);
        reinterpret_cast<u32*>(C1)[oi] =
            (u32)__bfloat16_as_ushort(x1) | ((u32)__bfloat16_as_ushort(y1) << 16);
    }
}

// ---------------- host entry ----------------
extern "C" void kernel_launch(void* const* d_in, const int* in_sizes, int n_in,
                              void* d_out, int out_size)
{
    const float* x  = (const float*)d_in[0];
    const float* Wq = (const float*)d_in[1];
    const float* bq = (const float*)d_in[2];
    const float* Wk = (const float*)d_in[3];
    const float* bk = (const float*)d_in[4];
    const float* Wv = (const float*)d_in[5];
    const float* bv = (const float*)d_in[6];
    const float* Wo = (const float*)d_in[7];
    const float* bo = (const float*)d_in[8];
    float* out = (float*)d_out;

    float *Qt, *Kt, *V, *PP, *FS, *WGT; int* DLY;
    __nv_bfloat16 *XS, *CS, *WS;
    cudaGetSymbolAddress((void**)&Qt,  g_Qt);
    cudaGetSymbolAddress((void**)&Kt,  g_Kt);
    cudaGetSymbolAddress((void**)&V,   g_V);
    cudaGetSymbolAddress((void**)&PP,  g_PP);
    cudaGetSymbolAddress((void**)&FS,  g_FS);
    cudaGetSymbolAddress((void**)&WGT, g_W);
    cudaGetSymbolAddress((void**)&DLY, g_D);
    cudaGetSymbolAddress((void**)&XS,  g_XS);
    cudaGetSymbolAddress((void**)&CS,  g_CS);
    cudaGetSymbolAddress((void**)&WS,  g_WS);

    const size_t NX = (size_t)MTOT * DM_;     // 8388608
    __nv_bfloat16* XSp[2] = {XS, XS + NX};
    __nv_bfloat16* CSp[2] = {CS, CS + NX};
    __nv_bfloat16* WOp0 = WS + (size_t)3 * 2 * NWEL;
    __nv_bfloat16* WOp1 = WOp0 + NWEL;

    const int SMEM = 2 * STAGE_BYTES;   // 98304 per CTA -> 2 CTAs/SM
    cudaFuncSetAttribute(gemm_qkv,    cudaFuncAttributeMaxDynamicSharedMemorySize, SMEM);
    cudaFuncSetAttribute(gemm_single, cudaFuncAttributeMaxDynamicSharedMemorySize, SMEM);
    cudaFuncSetAttribute(corr_fft_kernel,    cudaFuncAttributeMaxDynamicSharedMemorySize, 65536);
    cudaFuncSetAttribute(reduce_topk_kernel, cudaFuncAttributeMaxDynamicSharedMemorySize, 65536);

    // launch order: ncu captures launch #4 -> corr_fft there
    convert_all_kernel<<<9216, 256>>>(x, Wq, Wk, Wv, Wo, XSp[0], XSp[1], WS);               // 1
    setup_kernel<<<16, 256>>>();                                                             // 2
    gemm_qkv<<<dim3(256, 4, 3), 256, SMEM>>>(XSp[0], XSp[1], WS, bq, bk, bv, Qt, Kt, V);     // 3
    corr_fft_kernel<<<NSEQ, 512, 65536>>>(Qt, Kt, PP);                                       // 4 <- profiled
    sum_fs_kernel<<<dim3(NBH, 9), 256>>>(PP, FS);                                            // 5
    reduce_topk_kernel<<<NBH, 512, 65536>>>(FS, WGT, DLY);                                   // 6
    gather_kernel<<<B_ * (L_ / 4), 256>>>(V, WGT, DLY, CSp[0], CSp[1]);                      // 7
    gemm_single<<<dim3(256, 4, 1), 256, SMEM>>>(CSp[0], CSp[1], WOp0, WOp1, bo, out);        // 8
}

// round 14
// speedup vs baseline: 1.0286x; 1.0061x over previous
#include <cuda_runtime.h>
#include <cuda_bf16.h>
#include <math.h>
#include <cstdint>

// ---------------- problem constants ----------------
#define B_  4
#define L_  4096
#define DM_ 512
#define KTOP 16
#define NBH 32            // B*H
#define NF 2049           // L/2+1
#define MTOT (B_*L_)      // 16384
#define NSEQ (B_*DM_)     // 2048 FFT series
#define NWEL (DM_*DM_)    // 262144 weight elements

typedef unsigned long long u64;
typedef unsigned int u32;

// ---------------- scratch (static __device__, no allocation) ----------------
__device__ float g_Qt[(size_t)B_*DM_*L_];    // Q time-major [(b*512+n)*4096+t]
__device__ float g_Kt[(size_t)B_*DM_*L_];    // K time-major
__device__ float g_V [(size_t)MTOT*DM_];     // V channel-major
__device__ float g_PP[(size_t)NSEQ*NF*2];    // per-series partial cross-spectra
__device__ float g_FS[NBH*NF*2];             // summed cross-spectrum
__device__ float g_W [NBH*KTOP];
__device__ int   g_D [NBH*KTOP];
__device__ float2 g_TW[4096];                // FFT twiddles exp(-2πik/4096)
__device__ __nv_bfloat16 g_XS[2][(size_t)MTOT*DM_];   // x split limbs
__device__ __nv_bfloat16 g_CS[2][(size_t)MTOT*DM_];   // ctx split limbs (gather output)
__device__ __nv_bfloat16 g_WS[4][2][NWEL];            // Wq,Wk,Wv,Wo split limbs

// ---------------- helpers ----------------
__device__ __forceinline__ u32 smem_u32(const void* p) {
    u32 a;
    asm("{ .reg .u64 t; cvta.to.shared.u64 t, %1; cvt.u32.u64 %0, t; }" : "=r"(a) : "l"(p));
    return a;
}
#define SWZ(x) ((u32)(x) ^ ((((u32)(x)) >> 3) & 0x70))

__device__ __forceinline__ void cp16(u32 dst, const void* src) {
    asm volatile("cp.async.cg.shared.global [%0], [%1], 16;" :: "r"(dst), "l"(src));
}
__device__ __forceinline__ void cp_commit() {
    asm volatile("cp.async.commit_group;" ::: "memory");
}
__device__ __forceinline__ void cp_wait1() {
    asm volatile("cp.async.wait_group 1;" ::: "memory");
}
__device__ __forceinline__ void cp_wait0() {
    asm volatile("cp.async.wait_group 0;" ::: "memory");
}
__device__ __forceinline__ void ldm_x4(u32* r, u32 addr) {
    asm volatile("ldmatrix.sync.aligned.m8n8.x4.shared.b16 {%0,%1,%2,%3}, [%4];"
        : "=r"(r[0]), "=r"(r[1]), "=r"(r[2]), "=r"(r[3]) : "r"(addr));
}
__device__ __forceinline__ void mma16816(float* d, const u32* a, u32 b0, u32 b1) {
    asm volatile(
        "mma.sync.aligned.m16n8k16.row.col.f32.bf16.bf16.f32 "
        "{%0,%1,%2,%3}, {%4,%5,%6,%7}, {%8,%9}, {%0,%1,%2,%3};"
        : "+f"(d[0]), "+f"(d[1]), "+f"(d[2]), "+f"(d[3])
        : "r"(a[0]), "r"(a[1]), "r"(a[2]), "r"(a[3]), "r"(b0), "r"(b1));
}

// ---------------- fused limb-split converts: x (8192 blocks) + 4 W (1024) ---
__global__ void convert_all_kernel(const float* __restrict__ x,
    const float* __restrict__ Wq, const float* __restrict__ Wk,
    const float* __restrict__ Wv, const float* __restrict__ Wo,
    __nv_bfloat16* __restrict__ XS0, __nv_bfloat16* __restrict__ XS1,
    __nv_bfloat16* __restrict__ WS)
{
    const float* src;
    __nv_bfloat16 *d0, *d1;
    int i;
    if (blockIdx.x < 8192) {
        src = x; d0 = XS0; d1 = XS1;
        i = blockIdx.x * 256 + threadIdx.x;
    } else {
        const int wblk = blockIdx.x - 8192;
        const int w = wblk >> 8;
        src = (w == 0) ? Wq : (w == 1) ? Wk : (w == 2) ? Wv : Wo;
        d0 = WS + (size_t)w * 2 * NWEL;
        d1 = d0 + NWEL;
        i = (wblk & 255) * 256 + threadIdx.x;
    }
    const float4 v = reinterpret_cast<const float4*>(src)[i];
    const float f[4] = {v.x, v.y, v.z, v.w};
    unsigned short h0[4], h1[4];
    #pragma unroll
    for (int j = 0; j < 4; j++) {
        __nv_bfloat16 b0 = __float2bfloat16(f[j]);
        float r = f[j] - __bfloat162float(b0);
        __nv_bfloat16 b1 = __float2bfloat16(r);
        h0[j] = __bfloat16_as_ushort(b0);
        h1[j] = __bfloat16_as_ushort(b1);
    }
    reinterpret_cast<uint2*>(d0)[i] = make_uint2((u32)h0[0] | ((u32)h0[1] << 16), (u32)h0[2] | ((u32)h0[3] << 16));
    reinterpret_cast<uint2*>(d1)[i] = make_uint2((u32)h1[0] | ((u32)h1[1] << 16), (u32)h1[2] | ((u32)h1[3] << 16));
}

// ---------------- setup: twiddles ----------------
__global__ void setup_kernel() {
    const int i = blockIdx.x * blockDim.x + threadIdx.x;
    if (i < 4096) {
        const double ang = -6.283185307179586476925 * (double)i / 4096.0;
        g_TW[i] = make_float2((float)cos(ang), (float)sin(ang));
    }
}

// ---------------- mma.sync split-bf16 GEMM body (3-term: 00,01,10) ----------
// CTA tile 64x128, 256 threads (2x4 warps, 32x32 warp tiles), k-chunk 64.
// Stage 48KB, double-buffered -> 96KB/CTA => 2 CTAs resident per SM.
#define STAGE_BYTES 49152     // A: 2 limbs x 8KB, B: 2 limbs x 16KB
__device__ __forceinline__ void gemm_body(
    const __nv_bfloat16* __restrict__ A0, const __nv_bfloat16* __restrict__ A1,
    const __nv_bfloat16* __restrict__ B0, const __nv_bfloat16* __restrict__ B1,
    const float* __restrict__ bias, float* __restrict__ out,
    const int transp, char* smem)
{
    const u32 sbase = smem_u32(smem);

    const int tid  = threadIdx.x;
    const int wid  = tid >> 5;
    const int lane = tid & 31;
    const int wm   = (wid & 1) * 32;     // warp m offset
    const int wn   = (wid >> 1) * 32;    // warp n offset
    const int m0   = blockIdx.x * 64;
    const int n0   = blockIdx.y * 128;

    const __nv_bfloat16* Ap[2] = {A0, A1};
    const __nv_bfloat16* Bp[2] = {B0, B1};

    float d[2][4][4];
    #pragma unroll
    for (int i = 0; i < 2; i++)
        #pragma unroll
        for (int j = 0; j < 4; j++)
            #pragma unroll
            for (int q = 0; q < 4; q++) d[i][j][q] = 0.0f;

    auto load_chunk = [&](int c, int stage) {
        const int k0 = c * 64;
        const u32 sb = sbase + stage * STAGE_BYTES;
        #pragma unroll
        for (int t = 0; t < 2; t++) {
            const char* gA = reinterpret_cast<const char*>(Ap[t]) + ((size_t)m0 * 512 + k0) * 2;
            const u32 sA = sb + t * 8192;
            #pragma unroll
            for (int i = 0; i < 2; i++) {            // 512 16B units (64 rows)
                const int u = tid + i * 256;
                const int row = u >> 3, cu = u & 7;
                cp16(sA + SWZ(row * 128 + cu * 16), gA + (size_t)row * 1024 + cu * 16);
            }
            const char* gB = reinterpret_cast<const char*>(Bp[t]) + ((size_t)n0 * 512 + k0) * 2;
            const u32 sB = sb + 16384 + t * 16384;
            #pragma unroll
            for (int i = 0; i < 4; i++) {            // 1024 16B units (128 rows)
                const int u = tid + i * 256;
                const int row = u >> 3, cu = u & 7;
                cp16(sB + SWZ(row * 128 + cu * 16), gB + (size_t)row * 1024 + cu * 16);
            }
        }
    };

    auto compute_chunk = [&](int stage) {
        const u32 sb = sbase + stage * STAGE_BYTES;
        #pragma unroll
        for (int ks = 0; ks < 4; ks++) {
            u32 a[2][4], b0f[2][4], b1f[2][4];
            #pragma unroll
            for (int mt = 0; mt < 2; mt++) {
                const int row = wm + mt * 16 + (lane & 15);
                const int cb  = ks * 32 + ((lane >> 4) * 16);
                ldm_x4(a[mt], sb + SWZ(row * 128 + cb));
            }
            {
                const int mi  = lane >> 3;
                const int rw  = wn + (mi >> 1) * 8 + (lane & 7);
                const int cb  = ks * 32 + (mi & 1) * 16;
                #pragma unroll
                for (int ntp = 0; ntp < 2; ntp++) {
                    ldm_x4(b0f[ntp], sb + 16384 +         SWZ((rw + ntp * 16) * 128 + cb));
                    ldm_x4(b1f[ntp], sb + 16384 + 16384 + SWZ((rw + ntp * 16) * 128 + cb));
                }
            }
            #pragma unroll
            for (int mt = 0; mt < 2; mt++)
                #pragma unroll
                for (int nt = 0; nt < 4; nt++)
                    mma16816(d[mt][nt], a[mt], b0f[nt >> 1][(nt & 1) * 2], b0f[nt >> 1][(nt & 1) * 2 + 1]);
            #pragma unroll
            for (int mt = 0; mt < 2; mt++)
                #pragma unroll
                for (int nt = 0; nt < 4; nt++)
                    mma16816(d[mt][nt], a[mt], b1f[nt >> 1][(nt & 1) * 2], b1f[nt >> 1][(nt & 1) * 2 + 1]);
            #pragma unroll
            for (int mt = 0; mt < 2; mt++) {
                const int row = wm + mt * 16 + (lane & 15);
                const int cb  = ks * 32 + ((lane >> 4) * 16);
                ldm_x4(a[mt], sb + 8192 + SWZ(row * 128 + cb));
            }
            #pragma unroll
            for (int mt = 0; mt < 2; mt++)
                #pragma unroll
                for (int nt = 0; nt < 4; nt++)
                    mma16816(d[mt][nt], a[mt], b0f[nt >> 1][(nt & 1) * 2], b0f[nt >> 1][(nt & 1) * 2 + 1]);
        }
    };

    load_chunk(0, 0);
    cp_commit();
    for (int c = 0; c < 8; c++) {
        if (c < 7) { load_chunk(c + 1, (c + 1) & 1); cp_commit(); cp_wait1(); }
        else       { cp_wait0(); }
        __syncthreads();
        compute_chunk(c & 1);
        __syncthreads();
    }

    if (transp == 0) {
        #pragma unroll
        for (int mt = 0; mt < 2; mt++) {
            const size_t mg = (size_t)(m0 + wm + mt * 16 + (lane >> 2));
            #pragma unroll
            for (int nt = 0; nt < 4; nt++) {
                const int n = n0 + wn + nt * 8 + (lane & 3) * 2;
                const float b0v = __ldg(&bias[n]), b1v = __ldg(&bias[n + 1]);
                float2 v0 = make_float2(d[mt][nt][0] + b0v, d[mt][nt][1] + b1v);
                float2 v1 = make_float2(d[mt][nt][2] + b0v, d[mt][nt][3] + b1v);
                *reinterpret_cast<float2*>(&out[mg * 512 + n])       = v0;
                *reinterpret_cast<float2*>(&out[(mg + 8) * 512 + n]) = v1;
            }
        }
    } else {
        float* S = reinterpret_cast<float*>(smem);
        const int RS = 68;                  // multiple of 4: float4-aligned rows
        #pragma unroll
        for (int mt = 0; mt < 2; mt++) {
            const int ml = wm + mt * 16 + (lane >> 2);
            #pragma unroll
            for (int nt = 0; nt < 4; nt++) {
                const int nl = wn + nt * 8 + (lane & 3) * 2;
                const float b0v = __ldg(&bias[n0 + nl]), b1v = __ldg(&bias[n0 + nl + 1]);
                S[nl * RS + ml]           = d[mt][nt][0] + b0v;
                S[(nl + 1) * RS + ml]     = d[mt][nt][1] + b1v;
                S[nl * RS + ml + 8]       = d[mt][nt][2] + b0v;
                S[(nl + 1) * RS + ml + 8] = d[mt][nt][3] + b1v;
            }
        }
        __syncthreads();
        const int bI = m0 >> 12;
        const int t0 = m0 & 4095;
        const int r    = tid >> 1;          // 0..127: local n row
        const int half = tid & 1;           // 32-float half along t
        float* dp = &out[((size_t)bI * 512 + n0 + r) * 4096 + t0 + half * 32];
        const float* sp = &S[r * RS + half * 32];
        #pragma unroll
        for (int u = 0; u < 8; u++)
            reinterpret_cast<float4*>(dp)[u] = reinterpret_cast<const float4*>(sp)[u];
    }
}

// Fused Q/K/V projections: blockIdx.z selects weight/bias/output/layout.
__global__ void __launch_bounds__(256, 2) gemm_qkv(
    const __nv_bfloat16* __restrict__ A0, const __nv_bfloat16* __restrict__ A1,
    const __nv_bfloat16* __restrict__ WS,
    const float* __restrict__ bq, const float* __restrict__ bk, const float* __restrict__ bv,
    float* __restrict__ Qt, float* __restrict__ Kt, float* __restrict__ V)
{
    extern __shared__ char smem[];
    const int z = blockIdx.z;
    const __nv_bfloat16* B0 = WS + (size_t)z * 2 * NWEL;
    const __nv_bfloat16* B1 = B0 + NWEL;
    const float* bias = (z == 0) ? bq : (z == 1) ? bk : bv;
    float* out        = (z == 0) ? Qt : (z == 1) ? Kt : V;
    gemm_body(A0, A1, B0, B1, bias, out, (z == 2) ? 0 : 1, smem);
}

// Single GEMM (output projection), channel-major out.
__global__ void __launch_bounds__(256, 2) gemm_single(
    const __nv_bfloat16* __restrict__ A0, const __nv_bfloat16* __restrict__ A1,
    const __nv_bfloat16* __restrict__ B0, const __nv_bfloat16* __restrict__ B1,
    const float* __restrict__ bias, float* __restrict__ out)
{
    extern __shared__ char smem[];
    gemm_body(A0, A1, B0, B1, bias, out, 0, smem);
}

// ---------------- radix-16 Stockham FFT, N=4096, 3 stages, 256 threads ------
// Only stage-0 stores need a bank-rotation swizzle (phys0); stage-1 stores
// (spacing 16 = bank-pair period) and stage-2 accesses are naturally
// conflict-free. Result lands in the SECOND buffer (odd number of swaps).
__device__ __forceinline__ float2 cmul(float2 a, float2 w) {
    return make_float2(w.x * a.x - w.y * a.y, w.x * a.y + w.y * a.x);
}
__device__ __forceinline__ float2 cmulc(float2 a, float wr, float wi) {
    return make_float2(wr * a.x - wi * a.y, wr * a.y + wi * a.x);
}
__device__ __forceinline__ float2 cadd(float2 a, float2 b) { return make_float2(a.x + b.x, a.y + b.y); }
__device__ __forceinline__ float2 csub(float2 a, float2 b) { return make_float2(a.x - b.x, a.y - b.y); }
__device__ __forceinline__ int phys0(int p) {
    return (p & ~15) | ((p + (p >> 4)) & 15);
}

#define C8f 0.92387953251128674f
#define S8f 0.38268343236508977f
#define SQf 0.70710678118654752f

// natural-order DFT-16 in registers: 4xDFT4 -> W16 twiddle -> 4xDFT4
__device__ __forceinline__ void dft16(float2* c) {
    float2 y[4][4];
    #pragma unroll
    for (int n1 = 0; n1 < 4; n1++) {
        const float2 a0 = c[n1], a1 = c[n1 + 4], a2 = c[n1 + 8], a3 = c[n1 + 12];
        const float2 t0 = cadd(a0, a2), t1 = csub(a0, a2);
        const float2 t2 = cadd(a1, a3), t3 = csub(a1, a3);
        const float2 t3m = make_float2(t3.y, -t3.x);
        y[n1][0] = cadd(t0, t2); y[n1][1] = cadd(t1, t3m);
        y[n1][2] = csub(t0, t2); y[n1][3] = csub(t1, t3m);
    }
    // W16^{n1*k1}
    y[1][1] = cmulc(y[1][1],  C8f, -S8f);
    y[1][2] = cmulc(y[1][2],  SQf, -SQf);
    y[1][3] = cmulc(y[1][3],  S8f, -C8f);
    y[2][1] = cmulc(y[2][1],  SQf, -SQf);
    y[2][2] = make_float2(y[2][2].y, -y[2][2].x);     // * (-i)
    y[2][3] = cmulc(y[2][3], -SQf, -SQf);
    y[3][1] = cmulc(y[3][1],  S8f, -C8f);
    y[3][2] = cmulc(y[3][2], -SQf, -SQf);
    y[3][3] = cmulc(y[3][3], -C8f,  S8f);
    #pragma unroll
    for (int k1 = 0; k1 < 4; k1++) {
        const float2 a0 = y[0][k1], a1 = y[1][k1], a2 = y[2][k1], a3 = y[3][k1];
        const float2 t0 = cadd(a0, a2), t1 = csub(a0, a2);
        const float2 t2 = cadd(a1, a3), t3 = csub(a1, a3);
        const float2 t3m = make_float2(t3.y, -t3.x);
        c[k1]      = cadd(t0, t2);
        c[k1 + 4]  = cadd(t1, t3m);
        c[k1 + 8]  = csub(t0, t2);
        c[k1 + 12] = csub(t1, t3m);
    }
}

// input in A (natural), output in Bb (natural)
__device__ void fft4096(float2* A, float2* Bb) {
    const int j = threadIdx.x;          // 0..255
    float2 c[16];

    // stage 0: Ns=1, no twiddle; A natural -> Bb phys0
    #pragma unroll
    for (int q = 0; q < 16; q++) c[q] = A[j + q * 256];
    dft16(c);
    {
        const int base = j << 4;
        #pragma unroll
        for (int r = 0; r < 16; r++) Bb[phys0(base + r)] = c[r];
    }
    __syncthreads();

    // stage 1: Ns=16; Bb phys0 -> A natural
    {
        const int jm = j & 15;
        #pragma unroll
        for (int q = 0; q < 16; q++) c[q] = Bb[phys0(j + q * 256)];
        #pragma unroll
        for (int q = 1; q < 16; q++) c[q] = cmul(c[q], g_TW[(q * jm) << 4]);
        dft16(c);
        const int base = ((j >> 4) << 8) | jm;
        #pragma unroll
        for (int r = 0; r < 16; r++) A[base + (r << 4)] = c[r];
    }
    __syncthreads();

    // stage 2: Ns=256; A natural -> Bb natural
    {
        #pragma unroll
        for (int q = 0; q < 16; q++) c[q] = A[j + q * 256];
        #pragma unroll
        for (int q = 1; q < 16; q++) c[q] = cmul(c[q], g_TW[q * j]);
        dft16(c);
        #pragma unroll
        for (int r = 0; r < 16; r++) Bb[j + (r << 8)] = c[r];
    }
    __syncthreads();
}

// ---------------- forward FFTs -> per-series partial spectra ----------------
__global__ void corr_fft_kernel(const float* __restrict__ Qt, const float* __restrict__ Kt,
                                float* __restrict__ PP)
{
    extern __shared__ float2 sm[];
    float2* bufA = sm;
    float2* bufB = sm + 4096;
    const int seq = blockIdx.x;          // b*512 + h*64 + d
    const float* q = Qt + (size_t)seq * 4096;
    const float* k = Kt + (size_t)seq * 4096;
    float* pp = PP + (size_t)seq * NF * 2;

    #pragma unroll
    for (int r = 0; r < 16; r++) {
        const int t = threadIdx.x + r * 256;
        bufA[t] = make_float2(q[t], k[t]);
    }
    __syncthreads();

    fft4096(bufA, bufB);    // result in bufB

    for (int f = threadIdx.x; f <= 2048; f += 256) {
        const float2 Zf = bufB[f];
        const float2 Zm = bufB[(4096 - f) & 4095];
        const float qx = 0.5f * (Zf.x + Zm.x);
        const float qy = 0.5f * (Zf.y - Zm.y);
        const float kx = 0.5f * (Zf.y + Zm.y);
        const float ky = -0.5f * (Zf.x - Zm.x);
        pp[f * 2]     = qx * kx + qy * ky;
        pp[f * 2 + 1] = qy * kx - qx * ky;
    }
}

// ---------------- sum partials over d: FS[bh][f] = sum_d PP[bh*64+d][f] -----
__global__ void sum_fs_kernel(const float* __restrict__ PP, float* __restrict__ FS)
{
    const int bh = blockIdx.x;
    const int f  = blockIdx.y * 256 + threadIdx.x;
    if (f > 2048) return;
    const float* base = PP + ((size_t)bh * 64) * NF * 2 + f * 2;
    float sx = 0.0f, sy = 0.0f;
    #pragma unroll 8
    for (int d = 0; d < 64; d++) {
        sx += base[(size_t)d * NF * 2];
        sy += base[(size_t)d * NF * 2 + 1];
    }
    FS[(bh * NF + f) * 2]     = sx;
    FS[(bh * NF + f) * 2 + 1] = sy;
}

// ---------------- inverse FFT + top-k + softmax (shuffle reductions) --------
__global__ void reduce_topk_kernel(const float* __restrict__ FS,
                                   float* __restrict__ WGT, int* __restrict__ DLY)
{
    extern __shared__ float2 sm[];
    float2* bufA = sm;
    float2* bufB = sm + 4096;
    __shared__ float wv[8];
    __shared__ int   wi[8];
    __shared__ float topv[KTOP];
    __shared__ int   topi[KTOP];

    const int bh = blockIdx.x;
    const int tid = threadIdx.x;
    const int lane = tid & 31;
    const int wrp  = tid >> 5;

    for (int f = tid; f < 4096; f += 256) {
        float2 v;
        if (f <= 2048) {
            v.x =  FS[(bh * NF + f) * 2];
            v.y = -FS[(bh * NF + f) * 2 + 1];
        } else {
            const int fm = 4096 - f;
            v.x = FS[(bh * NF + fm) * 2];
            v.y = FS[(bh * NF + fm) * 2 + 1];
        }
        bufA[f] = v;
    }
    __syncthreads();

    fft4096(bufA, bufB);    // result in bufB

    float* cbuf = reinterpret_cast<float*>(bufA);
    const float scale = 1.0f / (4096.0f * 64.0f);
    for (int t = tid; t < 4096; t += 256) cbuf[t] = bufB[t].x * scale;
    __syncthreads();

    for (int it = 0; it < KTOP; it++) {
        float best = -1e30f; int bi = 0;
        #pragma unroll
        for (int r = 0; r < 16; r++) {
            const int t = tid + r * 256;
            const float v = cbuf[t];
            if (v > best || (v == best && t < bi)) { best = v; bi = t; }
        }
        #pragma unroll
        for (int off = 16; off > 0; off >>= 1) {
            const float ov = __shfl_xor_sync(0xFFFFFFFF, best, off);
            const int   oi = __shfl_xor_sync(0xFFFFFFFF, bi,   off);
            if (ov > best || (ov == best && oi < bi)) { best = ov; bi = oi; }
        }
        if (lane == 0) { wv[wrp] = best; wi[wrp] = bi; }
        __syncthreads();
        if (wrp == 0) {
            float v2 = (lane < 8) ? wv[lane] : -1e30f;
            int   i2 = (lane < 8) ? wi[lane] : 0;
            #pragma unroll
            for (int off = 4; off > 0; off >>= 1) {
                const float ov = __shfl_xor_sync(0xFFFFFFFF, v2, off);
                const int   oi = __shfl_xor_sync(0xFFFFFFFF, i2, off);
                if (ov > v2 || (ov == v2 && oi < i2)) { v2 = ov; i2 = oi; }
            }
            if (lane == 0) {
                topv[it] = v2; topi[it] = i2;
                cbuf[i2] = -1e30f;
            }
        }
        __syncthreads();
    }

    if (tid == 0) {
        float m = topv[0];
        #pragma unroll
        for (int j = 1; j < KTOP; j++) m = fmaxf(m, topv[j]);
        float e[KTOP]; float s = 0.0f;
        #pragma unroll
        for (int j = 0; j < KTOP; j++) { e[j] = expf(topv[j] - m); s += e[j]; }
        const float inv = 1.0f / s;
        #pragma unroll
        for (int j = 0; j < KTOP; j++) {
            WGT[bh * KTOP + j] = e[j] * inv;
            DLY[bh * KTOP + j] = topi[j];
        }
    }
}

// ---------------- delay gather: writes bf16 limb pair directly --------------
__global__ void __launch_bounds__(256) gather_kernel(
    const float* __restrict__ V, const float* __restrict__ WGT,
    const int* __restrict__ DLY,
    __nv_bfloat16* __restrict__ C0, __nv_bfloat16* __restrict__ C1)
{
    __shared__ float w[128];
    __shared__ int   dl[128];
    const int blk = blockIdx.x;
    const int b  = blk >> 10;
    const int t0 = (blk & 1023) * 4;
    const int tid = threadIdx.x;

    if (tid < 128) {
        const int h = tid >> 4, j = tid & 15;
        w[tid]  = WGT[(b * 8 + h) * KTOP + j];
        dl[tid] = DLY[(b * 8 + h) * KTOP + j];
    }
    __syncthreads();

    const int c2 = tid;                 // float2 channel index 0..255
    const int h  = c2 >> 5;
    const float* wp = &w[h * 16];
    const int*   dp = &dl[h * 16];
    const float2* Vb = reinterpret_cast<const float2*>(V + (size_t)b * 4096 * 512);

    #pragma unroll
    for (int tt = 0; tt < 4; tt++) {
        const int t = t0 + tt;
        float ax = 0.0f, ay = 0.0f;
        #pragma unroll
        for (int j = 0; j < 16; j++) {
            const int idx = (t - dp[j]) & 4095;
            const float2 v = Vb[(size_t)idx * 256 + c2];
            ax += wp[j] * v.x;
            ay += wp[j] * v.y;
        }
        const __nv_bfloat16 x0 = __float2bfloat16(ax);
        const __nv_bfloat16 x1 = __float2bfloat16(ax - __bfloat162float(x0));
        const __nv_bfloat16 y0 = __float2bfloat16(ay);
        const __nv_bfloat16 y1 = __float2bfloat16(ay - __bfloat162float(y0));
        const size_t oi = ((size_t)b * 4096 + t) * 256 + c2;
        reinterpret_cast<u32*>(C0)[oi] =
            (u32)__bfloat16_as_ushort(x0) | ((u32)__bfloat16_as_ushort(y0) << 16);
        reinterpret_cast<u32*>(C1)[oi] =
            (u32)__bfloat16_as_ushort(x1) | ((u32)__bfloat16_as_ushort(y1) << 16);
    }
}

// ---------------- host entry ----------------
extern "C" void kernel_launch(void* const* d_in, const int* in_sizes, int n_in,
                              void* d_out, int out_size)
{
    const float* x  = (const float*)d_in[0];
    const float* Wq = (const float*)d_in[1];
    const float* bq = (const float*)d_in[2];
    const float* Wk = (const float*)d_in[3];
    const float* bk = (const float*)d_in[4];
    const float* Wv = (const float*)d_in[5];
    const float* bv = (const float*)d_in[6];
    const float* Wo = (const float*)d_in[7];
    const float* bo = (const float*)d_in[8];
    float* out = (float*)d_out;

    float *Qt, *Kt, *V, *PP, *FS, *WGT; int* DLY;
    __nv_bfloat16 *XS, *CS, *WS;
    cudaGetSymbolAddress((void**)&Qt,  g_Qt);
    cudaGetSymbolAddress((void**)&Kt,  g_Kt);
    cudaGetSymbolAddress((void**)&V,   g_V);
    cudaGetSymbolAddress((void**)&PP,  g_PP);
    cudaGetSymbolAddress((void**)&FS,  g_FS);
    cudaGetSymbolAddress((void**)&WGT, g_W);
    cudaGetSymbolAddress((void**)&DLY, g_D);
    cudaGetSymbolAddress((void**)&XS,  g_XS);
    cudaGetSymbolAddress((void**)&CS,  g_CS);
    cudaGetSymbolAddress((void**)&WS,  g_WS);

    const size_t NX = (size_t)MTOT * DM_;     // 8388608
    __nv_bfloat16* XSp[2] = {XS, XS + NX};
    __nv_bfloat16* CSp[2] = {CS, CS + NX};
    __nv_bfloat16* WOp0 = WS + (size_t)3 * 2 * NWEL;
    __nv_bfloat16* WOp1 = WOp0 + NWEL;

    const int SMEM = 2 * STAGE_BYTES;   // 98304 per CTA -> 2 CTAs/SM
    cudaFuncSetAttribute(gemm_qkv,    cudaFuncAttributeMaxDynamicSharedMemorySize, SMEM);
    cudaFuncSetAttribute(gemm_single, cudaFuncAttributeMaxDynamicSharedMemorySize, SMEM);
    cudaFuncSetAttribute(corr_fft_kernel,    cudaFuncAttributeMaxDynamicSharedMemorySize, 65536);
    cudaFuncSetAttribute(reduce_topk_kernel, cudaFuncAttributeMaxDynamicSharedMemorySize, 65536);

    // launch order: ncu captures launch #4 -> corr_fft there
    convert_all_kernel<<<9216, 256>>>(x, Wq, Wk, Wv, Wo, XSp[0], XSp[1], WS);               // 1
    setup_kernel<<<16, 256>>>();                                                             // 2
    gemm_qkv<<<dim3(256, 4, 3), 256, SMEM>>>(XSp[0], XSp[1], WS, bq, bk, bv, Qt, Kt, V);     // 3
    corr_fft_kernel<<<NSEQ, 256, 65536>>>(Qt, Kt, PP);                                       // 4 <- profiled
    sum_fs_kernel<<<dim3(NBH, 9), 256>>>(PP, FS);                                            // 5
    reduce_topk_kernel<<<NBH, 256, 65536>>>(FS, WGT, DLY);                                   // 6
    gather_kernel<<<B_ * (L_ / 4), 256>>>(V, WGT, DLY, CSp[0], CSp[1]);                      // 7
    gemm_single<<<dim3(256, 4, 1), 256, SMEM>>>(CSp[0], CSp[1], WOp0, WOp1, bo, out);        // 8
}

// round 15
// speedup vs baseline: 1.0334x; 1.0047x over previous
#include <cuda_runtime.h>
#include <cuda_bf16.h>
#include <math.h>
#include <cstdint>

// ---------------- problem constants ----------------
#define B_  4
#define L_  4096
#define DM_ 512
#define KTOP 16
#define NBH 32            // B*H
#define NF 2049           // L/2+1
#define MTOT (B_*L_)      // 16384
#define NSEQ (B_*DM_)     // 2048 FFT series
#define NWEL (DM_*DM_)    // 262144 weight elements

typedef unsigned long long u64;
typedef unsigned int u32;

// ---------------- scratch (static __device__, no allocation) ----------------
__device__ float g_Qt[(size_t)B_*DM_*L_];    // Q time-major [(b*512+n)*4096+t]
__device__ float g_Kt[(size_t)B_*DM_*L_];    // K time-major
__device__ float g_V [(size_t)MTOT*DM_];     // V channel-major
__device__ float g_PP[(size_t)NSEQ*NF*2];    // per-series partial cross-spectra
__device__ float g_FS[NBH*NF*2];             // summed cross-spectrum
__device__ float g_W [NBH*KTOP];
__device__ int   g_D [NBH*KTOP];
__device__ float2 g_TW[4096];                // FFT twiddles exp(-2πik/4096)
__device__ __nv_bfloat16 g_XS[2][(size_t)MTOT*DM_];   // x split limbs
__device__ __nv_bfloat16 g_CS[2][(size_t)MTOT*DM_];   // ctx split limbs (gather output)
__device__ __nv_bfloat16 g_WS[4][2][NWEL];            // Wq,Wk,Wv,Wo split limbs

// ---------------- helpers ----------------
__device__ __forceinline__ u32 smem_u32(const void* p) {
    u32 a;
    asm("{ .reg .u64 t; cvta.to.shared.u64 t, %1; cvt.u32.u64 %0, t; }" : "=r"(a) : "l"(p));
    return a;
}
#define SWZ(x) ((u32)(x) ^ ((((u32)(x)) >> 3) & 0x70))

__device__ __forceinline__ void cp16(u32 dst, const void* src) {
    asm volatile("cp.async.cg.shared.global [%0], [%1], 16;" :: "r"(dst), "l"(src));
}
__device__ __forceinline__ void cp_commit() {
    asm volatile("cp.async.commit_group;" ::: "memory");
}
__device__ __forceinline__ void cp_wait1() {
    asm volatile("cp.async.wait_group 1;" ::: "memory");
}
__device__ __forceinline__ void cp_wait0() {
    asm volatile("cp.async.wait_group 0;" ::: "memory");
}
__device__ __forceinline__ void ldm_x4(u32* r, u32 addr) {
    asm volatile("ldmatrix.sync.aligned.m8n8.x4.shared.b16 {%0,%1,%2,%3}, [%4];"
        : "=r"(r[0]), "=r"(r[1]), "=r"(r[2]), "=r"(r[3]) : "r"(addr));
}
__device__ __forceinline__ void mma16816(float* d, const u32* a, u32 b0, u32 b1) {
    asm volatile(
        "mma.sync.aligned.m16n8k16.row.col.f32.bf16.bf16.f32 "
        "{%0,%1,%2,%3}, {%4,%5,%6,%7}, {%8,%9}, {%0,%1,%2,%3};"
        : "+f"(d[0]), "+f"(d[1]), "+f"(d[2]), "+f"(d[3])
        : "r"(a[0]), "r"(a[1]), "r"(a[2]), "r"(a[3]), "r"(b0), "r"(b1));
}

// ---------------- fused limb-split converts: x (8192 blocks) + 4 W (1024) ---
__global__ void convert_all_kernel(const float* __restrict__ x,
    const float* __restrict__ Wq, const float* __restrict__ Wk,
    const float* __restrict__ Wv, const float* __restrict__ Wo,
    __nv_bfloat16* __restrict__ XS0, __nv_bfloat16* __restrict__ XS1,
    __nv_bfloat16* __restrict__ WS)
{
    const float* src;
    __nv_bfloat16 *d0, *d1;
    int i;
    if (blockIdx.x < 8192) {
        src = x; d0 = XS0; d1 = XS1;
        i = blockIdx.x * 256 + threadIdx.x;
    } else {
        const int wblk = blockIdx.x - 8192;
        const int w = wblk >> 8;
        src = (w == 0) ? Wq : (w == 1) ? Wk : (w == 2) ? Wv : Wo;
        d0 = WS + (size_t)w * 2 * NWEL;
        d1 = d0 + NWEL;
        i = (wblk & 255) * 256 + threadIdx.x;
    }
    const float4 v = reinterpret_cast<const float4*>(src)[i];
    const float f[4] = {v.x, v.y, v.z, v.w};
    unsigned short h0[4], h1[4];
    #pragma unroll
    for (int j = 0; j < 4; j++) {
        __nv_bfloat16 b0 = __float2bfloat16(f[j]);
        float r = f[j] - __bfloat162float(b0);
        __nv_bfloat16 b1 = __float2bfloat16(r);
        h0[j] = __bfloat16_as_ushort(b0);
        h1[j] = __bfloat16_as_ushort(b1);
    }
    reinterpret_cast<uint2*>(d0)[i] = make_uint2((u32)h0[0] | ((u32)h0[1] << 16), (u32)h0[2] | ((u32)h0[3] << 16));
    reinterpret_cast<uint2*>(d1)[i] = make_uint2((u32)h1[0] | ((u32)h1[1] << 16), (u32)h1[2] | ((u32)h1[3] << 16));
}

// ---------------- setup: twiddles ----------------
__global__ void setup_kernel() {
    const int i = blockIdx.x * blockDim.x + threadIdx.x;
    if (i < 4096) {
        const double ang = -6.283185307179586476925 * (double)i / 4096.0;
        g_TW[i] = make_float2((float)cos(ang), (float)sin(ang));
    }
}

// ---------------- mma.sync split-bf16 GEMM body (3-term: 00,01,10) ----------
// CTA tile 64x128, 256 threads (2x4 warps, 32x32 warp tiles), k-chunk 64.
// Stage 48KB, double-buffered -> 96KB/CTA => 2 CTAs resident per SM.
#define STAGE_BYTES 49152     // A: 2 limbs x 8KB, B: 2 limbs x 16KB
__device__ __forceinline__ void gemm_body(
    const __nv_bfloat16* __restrict__ A0, const __nv_bfloat16* __restrict__ A1,
    const __nv_bfloat16* __restrict__ B0, const __nv_bfloat16* __restrict__ B1,
    const float* __restrict__ bias, float* __restrict__ out,
    const int transp, char* smem)
{
    const u32 sbase = smem_u32(smem);

    const int tid  = threadIdx.x;
    const int wid  = tid >> 5;
    const int lane = tid & 31;
    const int wm   = (wid & 1) * 32;     // warp m offset
    const int wn   = (wid >> 1) * 32;    // warp n offset
    const int m0   = blockIdx.x * 64;
    const int n0   = blockIdx.y * 128;

    const __nv_bfloat16* Ap[2] = {A0, A1};
    const __nv_bfloat16* Bp[2] = {B0, B1};

    float d[2][4][4];
    #pragma unroll
    for (int i = 0; i < 2; i++)
        #pragma unroll
        for (int j = 0; j < 4; j++)
            #pragma unroll
            for (int q = 0; q < 4; q++) d[i][j][q] = 0.0f;

    auto load_chunk = [&](int c, int stage) {
        const int k0 = c * 64;
        const u32 sb = sbase + stage * STAGE_BYTES;
        #pragma unroll
        for (int t = 0; t < 2; t++) {
            const char* gA = reinterpret_cast<const char*>(Ap[t]) + ((size_t)m0 * 512 + k0) * 2;
            const u32 sA = sb + t * 8192;
            #pragma unroll
            for (int i = 0; i < 2; i++) {            // 512 16B units (64 rows)
                const int u = tid + i * 256;
                const int row = u >> 3, cu = u & 7;
                cp16(sA + SWZ(row * 128 + cu * 16), gA + (size_t)row * 1024 + cu * 16);
            }
            const char* gB = reinterpret_cast<const char*>(Bp[t]) + ((size_t)n0 * 512 + k0) * 2;
            const u32 sB = sb + 16384 + t * 16384;
            #pragma unroll
            for (int i = 0; i < 4; i++) {            // 1024 16B units (128 rows)
                const int u = tid + i * 256;
                const int row = u >> 3, cu = u & 7;
                cp16(sB + SWZ(row * 128 + cu * 16), gB + (size_t)row * 1024 + cu * 16);
            }
        }
    };

    auto compute_chunk = [&](int stage) {
        const u32 sb = sbase + stage * STAGE_BYTES;
        #pragma unroll
        for (int ks = 0; ks < 4; ks++) {
            u32 a[2][4], b0f[2][4], b1f[2][4];
            #pragma unroll
            for (int mt = 0; mt < 2; mt++) {
                const int row = wm + mt * 16 + (lane & 15);
                const int cb  = ks * 32 + ((lane >> 4) * 16);
                ldm_x4(a[mt], sb + SWZ(row * 128 + cb));
            }
            {
                const int mi  = lane >> 3;
                const int rw  = wn + (mi >> 1) * 8 + (lane & 7);
                const int cb  = ks * 32 + (mi & 1) * 16;
                #pragma unroll
                for (int ntp = 0; ntp < 2; ntp++) {
                    ldm_x4(b0f[ntp], sb + 16384 +         SWZ((rw + ntp * 16) * 128 + cb));
                    ldm_x4(b1f[ntp], sb + 16384 + 16384 + SWZ((rw + ntp * 16) * 128 + cb));
                }
            }
            #pragma unroll
            for (int mt = 0; mt < 2; mt++)
                #pragma unroll
                for (int nt = 0; nt < 4; nt++)
                    mma16816(d[mt][nt], a[mt], b0f[nt >> 1][(nt & 1) * 2], b0f[nt >> 1][(nt & 1) * 2 + 1]);
            #pragma unroll
            for (int mt = 0; mt < 2; mt++)
                #pragma unroll
                for (int nt = 0; nt < 4; nt++)
                    mma16816(d[mt][nt], a[mt], b1f[nt >> 1][(nt & 1) * 2], b1f[nt >> 1][(nt & 1) * 2 + 1]);
            #pragma unroll
            for (int mt = 0; mt < 2; mt++) {
                const int row = wm + mt * 16 + (lane & 15);
                const int cb  = ks * 32 + ((lane >> 4) * 16);
                ldm_x4(a[mt], sb + 8192 + SWZ(row * 128 + cb));
            }
            #pragma unroll
            for (int mt = 0; mt < 2; mt++)
                #pragma unroll
                for (int nt = 0; nt < 4; nt++)
                    mma16816(d[mt][nt], a[mt], b0f[nt >> 1][(nt & 1) * 2], b0f[nt >> 1][(nt & 1) * 2 + 1]);
        }
    };

    load_chunk(0, 0);
    cp_commit();
    for (int c = 0; c < 8; c++) {
        if (c < 7) { load_chunk(c + 1, (c + 1) & 1); cp_commit(); cp_wait1(); }
        else       { cp_wait0(); }
        __syncthreads();
        compute_chunk(c & 1);
        __syncthreads();
    }

    if (transp == 0) {
        #pragma unroll
        for (int mt = 0; mt < 2; mt++) {
            const size_t mg = (size_t)(m0 + wm + mt * 16 + (lane >> 2));
            #pragma unroll
            for (int nt = 0; nt < 4; nt++) {
                const int n = n0 + wn + nt * 8 + (lane & 3) * 2;
                const float b0v = __ldg(&bias[n]), b1v = __ldg(&bias[n + 1]);
                float2 v0 = make_float2(d[mt][nt][0] + b0v, d[mt][nt][1] + b1v);
                float2 v1 = make_float2(d[mt][nt][2] + b0v, d[mt][nt][3] + b1v);
                *reinterpret_cast<float2*>(&out[mg * 512 + n])       = v0;
                *reinterpret_cast<float2*>(&out[(mg + 8) * 512 + n]) = v1;
            }
        }
    } else {
        float* S = reinterpret_cast<float*>(smem);
        const int RS = 68;                  // multiple of 4: float4-aligned rows
        #pragma unroll
        for (int mt = 0; mt < 2; mt++) {
            const int ml = wm + mt * 16 + (lane >> 2);
            #pragma unroll
            for (int nt = 0; nt < 4; nt++) {
                const int nl = wn + nt * 8 + (lane & 3) * 2;
                const float b0v = __ldg(&bias[n0 + nl]), b1v = __ldg(&bias[n0 + nl + 1]);
                S[nl * RS + ml]           = d[mt][nt][0] + b0v;
                S[(nl + 1) * RS + ml]     = d[mt][nt][1] + b1v;
                S[nl * RS + ml + 8]       = d[mt][nt][2] + b0v;
                S[(nl + 1) * RS + ml + 8] = d[mt][nt][3] + b1v;
            }
        }
        __syncthreads();
        const int bI = m0 >> 12;
        const int t0 = m0 & 4095;
        const int r    = tid >> 1;          // 0..127: local n row
        const int half = tid & 1;           // 32-float half along t
        float* dp = &out[((size_t)bI * 512 + n0 + r) * 4096 + t0 + half * 32];
        const float* sp = &S[r * RS + half * 32];
        #pragma unroll
        for (int u = 0; u < 8; u++)
            reinterpret_cast<float4*>(dp)[u] = reinterpret_cast<const float4*>(sp)[u];
    }
}

// Fused Q/K/V projections: blockIdx.z selects weight/bias/output/layout.
__global__ void __launch_bounds__(256, 2) gemm_qkv(
    const __nv_bfloat16* __restrict__ A0, const __nv_bfloat16* __restrict__ A1,
    const __nv_bfloat16* __restrict__ WS,
    const float* __restrict__ bq, const float* __restrict__ bk, const float* __restrict__ bv,
    float* __restrict__ Qt, float* __restrict__ Kt, float* __restrict__ V)
{
    extern __shared__ char smem[];
    const int z = blockIdx.z;
    const __nv_bfloat16* B0 = WS + (size_t)z * 2 * NWEL;
    const __nv_bfloat16* B1 = B0 + NWEL;
    const float* bias = (z == 0) ? bq : (z == 1) ? bk : bv;
    float* out        = (z == 0) ? Qt : (z == 1) ? Kt : V;
    gemm_body(A0, A1, B0, B1, bias, out, (z == 2) ? 0 : 1, smem);
}

// Single GEMM (output projection), channel-major out.
__global__ void __launch_bounds__(256, 2) gemm_single(
    const __nv_bfloat16* __restrict__ A0, const __nv_bfloat16* __restrict__ A1,
    const __nv_bfloat16* __restrict__ B0, const __nv_bfloat16* __restrict__ B1,
    const float* __restrict__ bias, float* __restrict__ out)
{
    extern __shared__ char smem[];
    gemm_body(A0, A1, B0, B1, bias, out, 0, smem);
}

// ---------------- radix-16 Stockham FFT, N=4096, 3 stages, 256 threads ------
// SINGLE-buffer in-place variant: each thread owns 16 points in registers, so
// read-all -> barrier -> write-all is race-free. 32KB smem/CTA doubles
// residency vs the ping-pong version. Only stage-0 stores (and their stage-1
// reads) need the phys0 bank rotation; all other accesses are conflict-free.
__device__ __forceinline__ float2 cmul(float2 a, float2 w) {
    return make_float2(w.x * a.x - w.y * a.y, w.x * a.y + w.y * a.x);
}
__device__ __forceinline__ float2 cmulc(float2 a, float wr, float wi) {
    return make_float2(wr * a.x - wi * a.y, wr * a.y + wi * a.x);
}
__device__ __forceinline__ float2 cadd(float2 a, float2 b) { return make_float2(a.x + b.x, a.y + b.y); }
__device__ __forceinline__ float2 csub(float2 a, float2 b) { return make_float2(a.x - b.x, a.y - b.y); }
__device__ __forceinline__ int phys0(int p) {
    return (p & ~15) | ((p + (p >> 4)) & 15);
}

#define C8f 0.92387953251128674f
#define S8f 0.38268343236508977f
#define SQf 0.70710678118654752f

// natural-order DFT-16 in registers: 4xDFT4 -> W16 twiddle -> 4xDFT4
__device__ __forceinline__ void dft16(float2* c) {
    float2 y[4][4];
    #pragma unroll
    for (int n1 = 0; n1 < 4; n1++) {
        const float2 a0 = c[n1], a1 = c[n1 + 4], a2 = c[n1 + 8], a3 = c[n1 + 12];
        const float2 t0 = cadd(a0, a2), t1 = csub(a0, a2);
        const float2 t2 = cadd(a1, a3), t3 = csub(a1, a3);
        const float2 t3m = make_float2(t3.y, -t3.x);
        y[n1][0] = cadd(t0, t2); y[n1][1] = cadd(t1, t3m);
        y[n1][2] = csub(t0, t2); y[n1][3] = csub(t1, t3m);
    }
    y[1][1] = cmulc(y[1][1],  C8f, -S8f);
    y[1][2] = cmulc(y[1][2],  SQf, -SQf);
    y[1][3] = cmulc(y[1][3],  S8f, -C8f);
    y[2][1] = cmulc(y[2][1],  SQf, -SQf);
    y[2][2] = make_float2(y[2][2].y, -y[2][2].x);
    y[2][3] = cmulc(y[2][3], -SQf, -SQf);
    y[3][1] = cmulc(y[3][1],  S8f, -C8f);
    y[3][2] = cmulc(y[3][2], -SQf, -SQf);
    y[3][3] = cmulc(y[3][3], -C8f,  S8f);
    #pragma unroll
    for (int k1 = 0; k1 < 4; k1++) {
        const float2 a0 = y[0][k1], a1 = y[1][k1], a2 = y[2][k1], a3 = y[3][k1];
        const float2 t0 = cadd(a0, a2), t1 = csub(a0, a2);
        const float2 t2 = cadd(a1, a3), t3 = csub(a1, a3);
        const float2 t3m = make_float2(t3.y, -t3.x);
        c[k1]      = cadd(t0, t2);
        c[k1 + 4]  = cadd(t1, t3m);
        c[k1 + 8]  = csub(t0, t2);
        c[k1 + 12] = csub(t1, t3m);
    }
}

// in-place over one 4096-point buffer; result natural order in A
__device__ void fft4096(float2* A) {
    const int j = threadIdx.x;          // 0..255
    float2 c[16];

    // stage 0: Ns=1; read natural, write phys0
    #pragma unroll
    for (int q = 0; q < 16; q++) c[q] = A[j + q * 256];
    dft16(c);
    __syncthreads();
    {
        const int base = j << 4;
        #pragma unroll
        for (int r = 0; r < 16; r++) A[phys0(base + r)] = c[r];
    }
    __syncthreads();

    // stage 1: Ns=16; read phys0, write natural (stride 16 -> conflict-free)
    {
        const int jm = j & 15;
        #pragma unroll
        for (int q = 0; q < 16; q++) c[q] = A[phys0(j + q * 256)];
        #pragma unroll
        for (int q = 1; q < 16; q++) c[q] = cmul(c[q], g_TW[(q * jm) << 4]);
        dft16(c);
        __syncthreads();
        const int base = ((j >> 4) << 8) | jm;
        #pragma unroll
        for (int r = 0; r < 16; r++) A[base + (r << 4)] = c[r];
    }
    __syncthreads();

    // stage 2: Ns=256; read natural, write natural (stride 256 -> conflict-free)
    {
        #pragma unroll
        for (int q = 0; q < 16; q++) c[q] = A[j + q * 256];
        #pragma unroll
        for (int q = 1; q < 16; q++) c[q] = cmul(c[q], g_TW[q * j]);
        dft16(c);
        __syncthreads();
        #pragma unroll
        for (int r = 0; r < 16; r++) A[j + (r << 8)] = c[r];
    }
    __syncthreads();
}

// ---------------- forward FFTs -> per-series partial spectra ----------------
__global__ void corr_fft_kernel(const float* __restrict__ Qt, const float* __restrict__ Kt,
                                float* __restrict__ PP)
{
    extern __shared__ float2 sm[];
    float2* buf = sm;                    // 4096 float2 = 32KB
    const int seq = blockIdx.x;          // b*512 + h*64 + d
    const float* q = Qt + (size_t)seq * 4096;
    const float* k = Kt + (size_t)seq * 4096;
    float* pp = PP + (size_t)seq * NF * 2;

    #pragma unroll
    for (int r = 0; r < 16; r++) {
        const int t = threadIdx.x + r * 256;
        buf[t] = make_float2(q[t], k[t]);
    }
    __syncthreads();

    fft4096(buf);

    for (int f = threadIdx.x; f <= 2048; f += 256) {
        const float2 Zf = buf[f];
        const float2 Zm = buf[(4096 - f) & 4095];
        const float qx = 0.5f * (Zf.x + Zm.x);
        const float qy = 0.5f * (Zf.y - Zm.y);
        const float kx = 0.5f * (Zf.y + Zm.y);
        const float ky = -0.5f * (Zf.x - Zm.x);
        pp[f * 2]     = qx * kx + qy * ky;
        pp[f * 2 + 1] = qy * kx - qx * ky;
    }
}

// ---------------- sum partials over d: FS[bh][f] = sum_d PP[bh*64+d][f] -----
__global__ void sum_fs_kernel(const float* __restrict__ PP, float* __restrict__ FS)
{
    const int bh = blockIdx.x;
    const int f  = blockIdx.y * 256 + threadIdx.x;
    if (f > 2048) return;
    const float* base = PP + ((size_t)bh * 64) * NF * 2 + f * 2;
    float sx = 0.0f, sy = 0.0f;
    #pragma unroll 8
    for (int d = 0; d < 64; d++) {
        sx += base[(size_t)d * NF * 2];
        sy += base[(size_t)d * NF * 2 + 1];
    }
    FS[(bh * NF + f) * 2]     = sx;
    FS[(bh * NF + f) * 2 + 1] = sy;
}

// ---------------- inverse FFT + top-k + softmax (shuffle reductions) --------
__global__ void reduce_topk_kernel(const float* __restrict__ FS,
                                   float* __restrict__ WGT, int* __restrict__ DLY)
{
    extern __shared__ float2 sm[];
    float2* buf  = sm;                                   // 32KB FFT buffer
    float*  cbuf = reinterpret_cast<float*>(sm + 4096);  // 16KB corr values
    __shared__ float wv[8];
    __shared__ int   wi[8];
    __shared__ float topv[KTOP];
    __shared__ int   topi[KTOP];

    const int bh = blockIdx.x;
    const int tid = threadIdx.x;
    const int lane = tid & 31;
    const int wrp  = tid >> 5;

    for (int f = tid; f < 4096; f += 256) {
        float2 v;
        if (f <= 2048) {
            v.x =  FS[(bh * NF + f) * 2];
            v.y = -FS[(bh * NF + f) * 2 + 1];
        } else {
            const int fm = 4096 - f;
            v.x = FS[(bh * NF + fm) * 2];
            v.y = FS[(bh * NF + fm) * 2 + 1];
        }
        buf[f] = v;
    }
    __syncthreads();

    fft4096(buf);

    const float scale = 1.0f / (4096.0f * 64.0f);
    for (int t = tid; t < 4096; t += 256) cbuf[t] = buf[t].x * scale;
    __syncthreads();

    for (int it = 0; it < KTOP; it++) {
        float best = -1e30f; int bi = 0;
        #pragma unroll
        for (int r = 0; r < 16; r++) {
            const int t = tid + r * 256;
            const float v = cbuf[t];
            if (v > best || (v == best && t < bi)) { best = v; bi = t; }
        }
        #pragma unroll
        for (int off = 16; off > 0; off >>= 1) {
            const float ov = __shfl_xor_sync(0xFFFFFFFF, best, off);
            const int   oi = __shfl_xor_sync(0xFFFFFFFF, bi,   off);
            if (ov > best || (ov == best && oi < bi)) { best = ov; bi = oi; }
        }
        if (lane == 0) { wv[wrp] = best; wi[wrp] = bi; }
        __syncthreads();
        if (wrp == 0) {
            float v2 = (lane < 8) ? wv[lane] : -1e30f;
            int   i2 = (lane < 8) ? wi[lane] : 0;
            #pragma unroll
            for (int off = 4; off > 0; off >>= 1) {
                const float ov = __shfl_xor_sync(0xFFFFFFFF, v2, off);
                const int   oi = __shfl_xor_sync(0xFFFFFFFF, i2, off);
                if (ov > v2 || (ov == v2 && oi < i2)) { v2 = ov; i2 = oi; }
            }
            if (lane == 0) {
                topv[it] = v2; topi[it] = i2;
                cbuf[i2] = -1e30f;
            }
        }
        __syncthreads();
    }

    if (tid == 0) {
        float m = topv[0];
        #pragma unroll
        for (int j = 1; j < KTOP; j++) m = fmaxf(m, topv[j]);
        float e[KTOP]; float s = 0.0f;
        #pragma unroll
        for (int j = 0; j < KTOP; j++) { e[j] = expf(topv[j] - m); s += e[j]; }
        const float inv = 1.0f / s;
        #pragma unroll
        for (int j = 0; j < KTOP; j++) {
            WGT[bh * KTOP + j] = e[j] * inv;
            DLY[bh * KTOP + j] = topi[j];
        }
    }
}

// ---------------- delay gather: writes bf16 limb pair directly --------------
__global__ void __launch_bounds__(256) gather_kernel(
    const float* __restrict__ V, const float* __restrict__ WGT,
    const int* __restrict__ DLY,
    __nv_bfloat16* __restrict__ C0, __nv_bfloat16* __restrict__ C1)
{
    __shared__ float w[128];
    __shared__ int   dl[128];
    const int blk = blockIdx.x;
    const int b  = blk >> 10;
    const int t0 = (blk & 1023) * 4;
    const int tid = threadIdx.x;

    if (tid < 128) {
        const int h = tid >> 4, j = tid & 15;
        w[tid]  = WGT[(b * 8 + h) * KTOP + j];
        dl[tid] = DLY[(b * 8 + h) * KTOP + j];
    }
    __syncthreads();

    const int c2 = tid;                 // float2 channel index 0..255
    const int h  = c2 >> 5;
    const float* wp = &w[h * 16];
    const int*   dp = &dl[h * 16];
    const float2* Vb = reinterpret_cast<const float2*>(V + (size_t)b * 4096 * 512);

    #pragma unroll
    for (int tt = 0; tt < 4; tt++) {
        const int t = t0 + tt;
        float ax = 0.0f, ay = 0.0f;
        #pragma unroll
        for (int j = 0; j < 16; j++) {
            const int idx = (t - dp[j]) & 4095;
            const float2 v = Vb[(size_t)idx * 256 + c2];
            ax += wp[j] * v.x;
            ay += wp[j] * v.y;
        }
        const __nv_bfloat16 x0 = __float2bfloat16(ax);
        const __nv_bfloat16 x1 = __float2bfloat16(ax - __bfloat162float(x0));
        const __nv_bfloat16 y0 = __float2bfloat16(ay);
        const __nv_bfloat16 y1 = __float2bfloat16(ay - __bfloat162float(y0));
        const size_t oi = ((size_t)b * 4096 + t) * 256 + c2;
        reinterpret_cast<u32*>(C0)[oi] =
            (u32)__bfloat16_as_ushort(x0) | ((u32)__bfloat16_as_ushort(y0) << 16);
        reinterpret_cast<u32*>(C1)[oi] =
            (u32)__bfloat16_as_ushort(x1) | ((u32)__bfloat16_as_ushort(y1) << 16);
    }
}

// ---------------- host entry ----------------
extern "C" void kernel_launch(void* const* d_in, const int* in_sizes, int n_in,
                              void* d_out, int out_size)
{
    const float* x  = (const float*)d_in[0];
    const float* Wq = (const float*)d_in[1];
    const float* bq = (const float*)d_in[2];
    const float* Wk = (const float*)d_in[3];
    const float* bk = (const float*)d_in[4];
    const float* Wv = (const float*)d_in[5];
    const float* bv = (const float*)d_in[6];
    const float* Wo = (const float*)d_in[7];
    const float* bo = (const float*)d_in[8];
    float* out = (float*)d_out;

    float *Qt, *Kt, *V, *PP, *FS, *WGT; int* DLY;
    __nv_bfloat16 *XS, *CS, *WS;
    cudaGetSymbolAddress((void**)&Qt,  g_Qt);
    cudaGetSymbolAddress((void**)&Kt,  g_Kt);
    cudaGetSymbolAddress((void**)&V,   g_V);
    cudaGetSymbolAddress((void**)&PP,  g_PP);
    cudaGetSymbolAddress((void**)&FS,  g_FS);
    cudaGetSymbolAddress((void**)&WGT, g_W);
    cudaGetSymbolAddress((void**)&DLY, g_D);
    cudaGetSymbolAddress((void**)&XS,  g_XS);
    cudaGetSymbolAddress((void**)&CS,  g_CS);
    cudaGetSymbolAddress((void**)&WS,  g_WS);

    const size_t NX = (size_t)MTOT * DM_;     // 8388608
    __nv_bfloat16* XSp[2] = {XS, XS + NX};
    __nv_bfloat16* CSp[2] = {CS, CS + NX};
    __nv_bfloat16* WOp0 = WS + (size_t)3 * 2 * NWEL;
    __nv_bfloat16* WOp1 = WOp0 + NWEL;

    const int SMEM = 2 * STAGE_BYTES;   // 98304 per CTA -> 2 CTAs/SM
    cudaFuncSetAttribute(gemm_qkv,    cudaFuncAttributeMaxDynamicSharedMemorySize, SMEM);
    cudaFuncSetAttribute(gemm_single, cudaFuncAttributeMaxDynamicSharedMemorySize, SMEM);
    cudaFuncSetAttribute(corr_fft_kernel,    cudaFuncAttributeMaxDynamicSharedMemorySize, 32768);
    cudaFuncSetAttribute(reduce_topk_kernel, cudaFuncAttributeMaxDynamicSharedMemorySize, 49152);

    // launch order: ncu captures launch #4 -> corr_fft there
    convert_all_kernel<<<9216, 256>>>(x, Wq, Wk, Wv, Wo, XSp[0], XSp[1], WS);               // 1
    setup_kernel<<<16, 256>>>();                                                             // 2
    gemm_qkv<<<dim3(256, 4, 3), 256, SMEM>>>(XSp[0], XSp[1], WS, bq, bk, bv, Qt, Kt, V);     // 3
    corr_fft_kernel<<<NSEQ, 256, 32768>>>(Qt, Kt, PP);                                       // 4 <- profiled
    sum_fs_kernel<<<dim3(NBH, 9), 256>>>(PP, FS);                                            // 5
    reduce_topk_kernel<<<NBH, 256, 49152>>>(FS, WGT, DLY);                                   // 6
    gather_kernel<<<B_ * (L_ / 4), 256>>>(V, WGT, DLY, CSp[0], CSp[1]);                      // 7
    gemm_single<<<dim3(256, 4, 1), 256, SMEM>>>(CSp[0], CSp[1], WOp0, WOp1, bo, out);        // 8
}